// round 14
// baseline (speedup 1.0000x reference)
#include <cuda_runtime.h>
#include <cuda_bf16.h>
#include <cstdint>

#define BATCH   4
#define NPTS    16384
#define CIN     128
#define NPOINT  1024
#define FG_NS   512
#define TOPK_K  2048
#define NCOLS2D 131072
#define NCOLS1D 65536
#define KX1     160

#define OFS_XYZ    0
#define OFS_FEAT   12288
#define OFS_IDX    (12288 + 1048576)
#define OFS_SCORES (12288 + 1048576 + 4096)

#define O_Y1D     0ull
#define O_Y1T     25165824ull
#define O_Y2T     41943040ull
#define O_P3MAX   58720256ull
#define O_P3MIN   59768832ull
#define O_MARGIN  60817408ull
#define O_NEWXYZ  60882944ull
#define O_FGMASK  60895232ull
#define O_INDICES 60960768ull
#define O_BALL    60964864ull
#define O_WPAD    61095936ull
#define O_FEATT   61116416ull
#define O_FPSPID  69505024ull
#define SCRATCH_FLOATS 69619712ull

__device__ float g_scratch[SCRATCH_FLOATS];
__device__ double g_sum[4][256];
__device__ double g_sumsq[4][256];

// ---------------------------------------------------------------------------
__device__ __forceinline__ float tf32r(float x) {
    uint32_t u;
    asm("cvt.rna.tf32.f32 %0, %1;" : "=r"(u) : "f"(x));
    return __uint_as_float(u);
}
__device__ __forceinline__ void mma_tf32(float* c, uint32_t a0, uint32_t a1,
                                         uint32_t a2, uint32_t a3,
                                         uint32_t b0, uint32_t b1) {
    asm("mma.sync.aligned.m16n8k8.row.col.f32.tf32.tf32.f32 "
        "{%0,%1,%2,%3},{%4,%5,%6,%7},{%8,%9},{%0,%1,%2,%3};"
        : "+f"(c[0]), "+f"(c[1]), "+f"(c[2]), "+f"(c[3])
        : "r"(a0), "r"(a1), "r"(a2), "r"(a3), "r"(b0), "r"(b1));
}
__device__ __forceinline__ void bn_affine(int layer, int m, double cnt,
                                          const float* g, const float* beta,
                                          float& a, float& c) {
    double mu = g_sum[layer][m] / cnt;
    double var = g_sumsq[layer][m] / cnt - mu * mu;
    a = g[m] * rsqrtf((float)var + 1e-5f);
    c = beta[m] - (float)mu * a;
}
// packed f32x2 helpers (per-element .rn == scalar rn)
__device__ __forceinline__ unsigned long long pk2(float lo, float hi) {
    unsigned long long r;
    asm("mov.b64 %0, {%1, %2};" : "=l"(r) : "f"(lo), "f"(hi));
    return r;
}
__device__ __forceinline__ unsigned long long add2(unsigned long long a,
                                                   unsigned long long b) {
    unsigned long long d;
    asm("add.rn.f32x2 %0, %1, %2;" : "=l"(d) : "l"(a), "l"(b));
    return d;
}
__device__ __forceinline__ unsigned long long mul2(unsigned long long a,
                                                   unsigned long long b) {
    unsigned long long d;
    asm("mul.rn.f32x2 %0, %1, %2;" : "=l"(d) : "l"(a), "l"(b));
    return d;
}
__device__ __forceinline__ unsigned long long fma2(unsigned long long a,
                                                   unsigned long long b,
                                                   unsigned long long c) {
    unsigned long long d;
    asm("fma.rn.f32x2 %0, %1, %2, %3;" : "=l"(d) : "l"(a), "l"(b), "l"(c));
    return d;
}
__device__ __forceinline__ void upk2(unsigned long long v, float& lo, float& hi) {
    asm("mov.b64 {%0, %1}, %2;" : "=f"(lo), "=f"(hi) : "l"(v));
}

// ---------------------------------------------------------------------------
// prep: zero stats + build PERMUTED padded w1 ([feat(128) | xyz(3) | pad])
// ---------------------------------------------------------------------------
__global__ void prep_kernel(const float* __restrict__ w1, float* __restrict__ wpad) {
    int t = blockIdx.x * blockDim.x + threadIdx.x;   // 20480 = 128*160
    if (blockIdx.x == 0) {
        double* s  = &g_sum[0][0];
        double* s2 = &g_sumsq[0][0];
        for (int i = threadIdx.x; i < 4 * 256; i += 256) { s[i] = 0.0; s2[i] = 0.0; }
    }
    int o = t / KX1, c = t % KX1;
    float v = 0.f;
    if (c < 128)       v = w1[o * 131 + c + 3];
    else if (c < 131)  v = w1[o * 131 + c - 128];
    wpad[t] = v;
}

__global__ void transpose_kernel(const float* __restrict__ features,
                                 float* __restrict__ featT)
{
    __shared__ float tile[32][33];
    int b = blockIdx.z;
    int n0 = blockIdx.x * 32, c0 = blockIdx.y * 32;
    int x = threadIdx.x, y = threadIdx.y;
#pragma unroll
    for (int k = 0; k < 32; k += 8)
        tile[y + k][x] = features[((size_t)b * CIN + c0 + y + k) * NPTS + n0 + x];
    __syncthreads();
#pragma unroll
    for (int k = 0; k < 32; k += 8)
        featT[((size_t)b * NPTS + n0 + y + k) * CIN + c0 + x] = tile[x][y + k];
}

// ---------------------------------------------------------------------------
// tf32 mma.sync conv GEMM. Tile = 128 rows x NT cols.
// ---------------------------------------------------------------------------
template<int KE, int NT, int AFF, int STATS, int POOL, int GB>
__global__ void __launch_bounds__(256, (NT == 64) ? 2 : 1) conv_mma(
    const float* __restrict__ W, const float* __restrict__ Xin,
    float* __restrict__ Yout, float* __restrict__ poolMax, float* __restrict__ poolMin,
    const float* __restrict__ gPrev, const float* __restrict__ bPrev,
    const int* __restrict__ ballIdx, const float* __restrict__ xyzIn,
    const float* __restrict__ newxyz)
{
    constexpr int LDK = KE + 4;
    constexpr int NWN = (NT == 128) ? 4 : 2;
    constexpr int MA  = (NT == 128) ? 4 : 2;
    extern __shared__ float sm[];
    float* As = sm;                     // [128][LDK]
    float* Bs = sm + 128 * LDK;         // [NT][LDK]
    __shared__ __align__(16) float affA[128];
    __shared__ __align__(16) float affC[128];
    const int tid = threadIdx.x;
    const int wid = tid >> 5, lane = tid & 31;
    const int g = lane >> 2, t = lane & 3;
    const int wm = wid / NWN, wn = wid % NWN;
    const int rowBase = blockIdx.y * 128;
    const int colBase = blockIdx.x * NT;

    if (AFF >= 0) {
        if (tid < 128)
            bn_affine(AFF, tid, (double)NCOLS2D, gPrev, bPrev, affA[tid], affC[tid]);
        __syncthreads();
    }
    for (int i = tid; i < 128 * (KE / 4); i += 256) {
        int r = i / (KE / 4), k = (i % (KE / 4)) * 4;
        float4 v = *(const float4*)(W + (size_t)(rowBase + r) * KE + k);
        As[r * LDK + k + 0] = tf32r(v.x);
        As[r * LDK + k + 1] = tf32r(v.y);
        As[r * LDK + k + 2] = tf32r(v.z);
        As[r * LDK + k + 3] = tf32r(v.w);
    }
    for (int i = tid; i < NT * (KE / 4); i += 256) {
        int r = i / (KE / 4), k = (i % (KE / 4)) * 4;
        float4 v;
        if (GB) {
            int col = colBase + r;
            int idx = ballIdx[col];
            int bb = col >> 15;
            if (k < 128) {
                v = *(const float4*)(Xin + ((size_t)(bb * NPTS + idx)) * 128 + k);
            } else if (k == 128) {
                int q = col >> 5;
                const float* xp = xyzIn + ((size_t)bb * NPTS + idx) * 3;
                v.x = __fsub_rn(xp[0], newxyz[q * 3 + 0]);
                v.y = __fsub_rn(xp[1], newxyz[q * 3 + 1]);
                v.z = __fsub_rn(xp[2], newxyz[q * 3 + 2]);
                v.w = 0.f;
            } else {
                v = make_float4(0.f, 0.f, 0.f, 0.f);
            }
        } else {
            v = *(const float4*)(Xin + (size_t)(colBase + r) * KE + k);
            if (AFF >= 0) {
                float4 av = *(const float4*)&affA[k];
                float4 cv = *(const float4*)&affC[k];
                v.x = fmaxf(fmaf(av.x, v.x, cv.x), 0.f);
                v.y = fmaxf(fmaf(av.y, v.y, cv.y), 0.f);
                v.z = fmaxf(fmaf(av.z, v.z, cv.z), 0.f);
                v.w = fmaxf(fmaf(av.w, v.w, cv.w), 0.f);
            }
        }
        Bs[r * LDK + k + 0] = tf32r(v.x);
        Bs[r * LDK + k + 1] = tf32r(v.y);
        Bs[r * LDK + k + 2] = tf32r(v.z);
        Bs[r * LDK + k + 3] = tf32r(v.w);
    }
    __syncthreads();

    float acc[MA][4][4];
#pragma unroll
    for (int i = 0; i < MA; i++)
#pragma unroll
        for (int j = 0; j < 4; j++)
#pragma unroll
            for (int c = 0; c < 4; c++) acc[i][j][c] = 0.f;

    const float* Arow0 = As + (size_t)(wm * (MA * 16) + g) * LDK + t;
    const float* Arow8 = Arow0 + 8 * LDK;
    const float* Bcol0 = Bs + (size_t)(wn * 32 + g) * LDK + t;

#pragma unroll 4
    for (int ks = 0; ks < KE / 8; ks++) {
        const int k0 = ks * 8;
        uint32_t a[MA][4], b[4][2];
#pragma unroll
        for (int ma = 0; ma < MA; ma++) {
            const float* p0 = Arow0 + ma * 16 * LDK + k0;
            const float* p8 = Arow8 + ma * 16 * LDK + k0;
            a[ma][0] = __float_as_uint(p0[0]);
            a[ma][1] = __float_as_uint(p8[0]);
            a[ma][2] = __float_as_uint(p0[4]);
            a[ma][3] = __float_as_uint(p8[4]);
        }
#pragma unroll
        for (int nb = 0; nb < 4; nb++) {
            const float* pb = Bcol0 + nb * 8 * LDK + k0;
            b[nb][0] = __float_as_uint(pb[0]);
            b[nb][1] = __float_as_uint(pb[4]);
        }
#pragma unroll
        for (int ma = 0; ma < MA; ma++)
#pragma unroll
            for (int nb = 0; nb < 4; nb++)
                mma_tf32(acc[ma][nb], a[ma][0], a[ma][1], a[ma][2], a[ma][3],
                         b[nb][0], b[nb][1]);
    }

#pragma unroll
    for (int ma = 0; ma < MA; ma++) {
        int r0 = wm * (MA * 16) + ma * 16 + g;
        float s0 = 0.f, q0 = 0.f, s1 = 0.f, q1 = 0.f;
        float mx0 = -1e30f, mn0 = 1e30f, mx1 = -1e30f, mn1 = 1e30f;
#pragma unroll
        for (int nb = 0; nb < 4; nb++) {
            float c0 = acc[ma][nb][0], c1 = acc[ma][nb][1];
            float c2 = acc[ma][nb][2], c3 = acc[ma][nb][3];
            s0 += c0 + c1; q0 = fmaf(c0, c0, fmaf(c1, c1, q0));
            s1 += c2 + c3; q1 = fmaf(c2, c2, fmaf(c3, c3, q1));
            if (POOL) {
                mx0 = fmaxf(mx0, fmaxf(c0, c1)); mn0 = fminf(mn0, fminf(c0, c1));
                mx1 = fmaxf(mx1, fmaxf(c2, c3)); mn1 = fminf(mn1, fminf(c2, c3));
            }
        }
#pragma unroll
        for (int off = 1; off < 4; off <<= 1) {
            s0 += __shfl_xor_sync(0xFFFFFFFFu, s0, off);
            q0 += __shfl_xor_sync(0xFFFFFFFFu, q0, off);
            s1 += __shfl_xor_sync(0xFFFFFFFFu, s1, off);
            q1 += __shfl_xor_sync(0xFFFFFFFFu, q1, off);
            if (POOL) {
                mx0 = fmaxf(mx0, __shfl_xor_sync(0xFFFFFFFFu, mx0, off));
                mn0 = fminf(mn0, __shfl_xor_sync(0xFFFFFFFFu, mn0, off));
                mx1 = fmaxf(mx1, __shfl_xor_sync(0xFFFFFFFFu, mx1, off));
                mn1 = fminf(mn1, __shfl_xor_sync(0xFFFFFFFFu, mn1, off));
            }
        }
        if (t == 0) {
            atomicAdd(&g_sum[STATS][rowBase + r0], (double)s0);
            atomicAdd(&g_sumsq[STATS][rowBase + r0], (double)q0);
            atomicAdd(&g_sum[STATS][rowBase + r0 + 8], (double)s1);
            atomicAdd(&g_sumsq[STATS][rowBase + r0 + 8], (double)q1);
            if (POOL) {
                int cent = (colBase >> 5) + wn;
                poolMax[(size_t)(rowBase + r0) * 4096 + cent] = mx0;
                poolMin[(size_t)(rowBase + r0) * 4096 + cent] = mn0;
                poolMax[(size_t)(rowBase + r0 + 8) * 4096 + cent] = mx1;
                poolMin[(size_t)(rowBase + r0 + 8) * 4096 + cent] = mn1;
            }
        }
    }

    if (!POOL) {
        __syncthreads();
        float* Ct = As;   // [NT cols][132]
#pragma unroll
        for (int ma = 0; ma < MA; ma++) {
            int r0 = wm * (MA * 16) + ma * 16 + g;
#pragma unroll
            for (int nb = 0; nb < 4; nb++) {
                int col0 = wn * 32 + nb * 8 + 2 * t;
                Ct[col0 * 132 + r0]           = acc[ma][nb][0];
                Ct[(col0 + 1) * 132 + r0]     = acc[ma][nb][1];
                Ct[col0 * 132 + r0 + 8]       = acc[ma][nb][2];
                Ct[(col0 + 1) * 132 + r0 + 8] = acc[ma][nb][3];
            }
        }
        __syncthreads();
        for (int i = tid; i < NT * 32; i += 256) {
            int col = i >> 5;
            int r4 = (i & 31) * 4;
            float4 v = *(float4*)&Ct[col * 132 + r4];
            *(float4*)(Yout + (size_t)(colBase + col) * 128 + r4) = v;
        }
    }
}

// ---------------------------------------------------------------------------
// SIMT SGEMM for mask-head conv — fp32 exact via packed fma.rn.f32x2
// ---------------------------------------------------------------------------
template<int RT>
__global__ void __launch_bounds__(256, 2) gemm_fused(
    const float* __restrict__ A, const float* __restrict__ B, float* __restrict__ C,
    int K, int Ncols, int statsLayer)
{
    constexpr int TM = RT * 16;
    __shared__ float As[2][16][TM + 4];
    __shared__ __align__(16) float Bs[2][16][128];
    const int tid = threadIdx.x;
    const int tx = tid & 15, ty = tid >> 4;
    const int rowBase = blockIdx.y * TM;
    const int colBase = blockIdx.x * 128;

    unsigned long long acc2[RT][4];
#pragma unroll
    for (int i = 0; i < RT; i++)
#pragma unroll
        for (int j = 0; j < 4; j++) acc2[i][j] = 0ull;

    const int ktiles = K >> 4;
    {
#pragma unroll
        for (int l = 0; l < RT; l++) {
            int i = l * 256 + tid;
            int r = i >> 4, kk = i & 15;
            As[0][kk][r] = A[(rowBase + r) * K + kk];
        }
#pragma unroll
        for (int l = 0; l < 2; l++) {
            int i = l * 256 + tid;
            int kk = i >> 5, c4 = i & 31;
            int gc = colBase + c4 * 4;
            const float* src = B + (((size_t)(gc >> 14) * 128 + kk) << 14) + (gc & 16383);
            *(float4*)&Bs[0][kk][c4 * 4] = *(const float4*)src;
        }
    }
    __syncthreads();

    float pa[RT];
    float4 pb0, pb1;
    for (int kt = 0; kt < ktiles; kt++) {
        const int cur = kt & 1, nxt = cur ^ 1;
        const bool more = (kt + 1 < ktiles);
        if (more) {
            const int k0 = (kt + 1) << 4;
#pragma unroll
            for (int l = 0; l < RT; l++) {
                int i = l * 256 + tid;
                int r = i >> 4, kk = i & 15;
                pa[l] = A[(rowBase + r) * K + k0 + kk];
            }
#pragma unroll
            for (int l = 0; l < 2; l++) {
                int i = l * 256 + tid;
                int kk = i >> 5, c4 = i & 31;
                int gk = k0 + kk, gc = colBase + c4 * 4;
                const float* src = B + (((size_t)(gc >> 14) * 128 + gk) << 14) + (gc & 16383);
                float4 v = *(const float4*)src;
                if (l == 0) pb0 = v; else pb1 = v;
            }
        }
#pragma unroll
        for (int kk = 0; kk < 16; kk++) {
            const unsigned long long* rbp =
                (const unsigned long long*)&Bs[cur][kk][tx * 8];
            unsigned long long rb2[4];
#pragma unroll
            for (int j = 0; j < 4; j++) rb2[j] = rbp[j];
#pragma unroll
            for (int i = 0; i < RT; i++) {
                float av = As[cur][kk][ty * RT + i];
                unsigned long long ra2 = pk2(av, av);
#pragma unroll
                for (int j = 0; j < 4; j++)
                    acc2[i][j] = fma2(ra2, rb2[j], acc2[i][j]);
            }
        }
        if (more) {
#pragma unroll
            for (int l = 0; l < RT; l++) {
                int i = l * 256 + tid;
                int r = i >> 4, kk = i & 15;
                As[nxt][kk][r] = pa[l];
            }
            { int kk = tid >> 5, c4 = tid & 31; *(float4*)&Bs[nxt][kk][c4 * 4] = pb0; }
            { int i = 256 + tid; int kk = i >> 5, c4 = i & 31; *(float4*)&Bs[nxt][kk][c4 * 4] = pb1; }
        }
        __syncthreads();
    }
    float acc[RT][8];
#pragma unroll
    for (int i = 0; i < RT; i++)
#pragma unroll
        for (int j = 0; j < 4; j++)
            upk2(acc2[i][j], acc[i][2 * j], acc[i][2 * j + 1]);
#pragma unroll
    for (int i = 0; i < RT; i++) {
        float* dst = C + (size_t)(rowBase + ty * RT + i) * Ncols + colBase + tx * 8;
        *(float4*)dst       = make_float4(acc[i][0], acc[i][1], acc[i][2], acc[i][3]);
        *(float4*)(dst + 4) = make_float4(acc[i][4], acc[i][5], acc[i][6], acc[i][7]);
    }
#pragma unroll
    for (int i = 0; i < RT; i++) {
        float s = 0.f, s2 = 0.f;
#pragma unroll
        for (int j = 0; j < 8; j++) { float v = acc[i][j]; s += v; s2 = fmaf(v, v, s2); }
#pragma unroll
        for (int off = 1; off < 16; off <<= 1) {
            s  += __shfl_xor_sync(0xFFFFFFFFu, s, off);
            s2 += __shfl_xor_sync(0xFFFFFFFFu, s2, off);
        }
        if (tx == 0) {
            int gr = rowBase + ty * RT + i;
            atomicAdd(&g_sum[statsLayer][gr], (double)s);
            atomicAdd(&g_sumsq[statsLayer][gr], (double)s2);
        }
    }
}

// ---------------------------------------------------------------------------
// mask head (BN0 finalize fused)
// ---------------------------------------------------------------------------
__global__ void maskhead_kernel(const float* __restrict__ y1d,
                                const float* __restrict__ fg1,
                                const float* __restrict__ fb1,
                                const float* __restrict__ fw2,
                                const float* __restrict__ fbias2,
                                float* __restrict__ outScores,
                                float* __restrict__ margin)
{
    __shared__ float affA[64], affC[64];
    if (threadIdx.x < 64)
        bn_affine(0, threadIdx.x, (double)NCOLS1D, fg1, fb1,
                  affA[threadIdx.x], affC[threadIdx.x]);
    __syncthreads();
    int col = blockIdx.x * blockDim.x + threadIdx.x;
    int b = col >> 14, n = col & 16383;
    float s0 = fbias2[0], s1 = fbias2[1];
#pragma unroll 4
    for (int c = 0; c < 64; c++) {
        float v = fmaxf(fmaf(affA[c], y1d[(size_t)c * NCOLS1D + col], affC[c]), 0.f);
        s0 = fmaf(fw2[c], v, s0);
        s1 = fmaf(fw2[64 + c], v, s1);
    }
    outScores[b * 32768 + n]         = s0;
    outScores[b * 32768 + 16384 + n] = s1;
    float mx = fmaxf(s0, s1);
    float e0 = expf(s0 - mx), e1 = expf(s1 - mx);
    margin[col] = (e1 - e0) / (e0 + e1);
}

// ---------------------------------------------------------------------------
// exact top-2048 per batch (radix select on 64-bit key)
// ---------------------------------------------------------------------------
__device__ __forceinline__ unsigned long long makeKey(float f, int i)
{
    unsigned u = __float_as_uint(f);
    u = (u & 0x80000000u) ? ~u : (u | 0x80000000u);
    return ((unsigned long long)u << 32) | (unsigned)(0xFFFFFFFFu - (unsigned)i);
}

__global__ void select_kernel(const float* __restrict__ margin, int* __restrict__ fgmask)
{
    __shared__ unsigned hist[256];
    __shared__ unsigned long long sprefix;
    __shared__ int skrem;
    int b = blockIdx.x, tid = threadIdx.x;
    const float* M = margin + b * NPTS;
    if (tid == 0) { sprefix = 0ull; skrem = TOPK_K; }
    __syncthreads();
    for (int pos = 56; pos >= 0; pos -= 8) {
        hist[tid] = 0;
        __syncthreads();
        unsigned long long pref = sprefix;
        for (int i = tid; i < NPTS; i += 256) {
            unsigned long long key = makeKey(M[i], i);
            bool act = (pos == 56) || ((key >> (pos + 8)) == (pref >> (pos + 8)));
            if (act) atomicAdd(&hist[(unsigned)(key >> pos) & 255u], 1u);
        }
        __syncthreads();
        if (tid == 0) {
            int k = skrem;
            int v = 255;
            while (v > 0 && (int)hist[v] < k) { k -= (int)hist[v]; v--; }
            skrem = k;
            sprefix = pref | ((unsigned long long)(unsigned)v << pos);
        }
        __syncthreads();
    }
    unsigned long long kth = sprefix;
    for (int i = tid; i < NPTS; i += 256)
        fgmask[b * NPTS + i] = (makeKey(M[i], i) >= kth) ? 1 : 0;
}

// ---------------------------------------------------------------------------
// masked FPS v5: Morton sort, HALF-warp box pruning (boxes in smem),
// f32x2 packed math, one barrier/iter. Exact.
// Half A = pairs 0..3 (256 slots), half B = pairs 4..6 (192 slots).
// ---------------------------------------------------------------------------
#define WSLOT 448
#define NPAIR 7
#define HA 4              // pairs in half A

__device__ __forceinline__ int spread3(int v) {
    return (v & 1) | ((v & 2) << 2) | ((v & 4) << 4);
}
__device__ __forceinline__ int cellOf(float x, float y, float z) {
    int cx = min(7, max(0, (int)(x * 8.f)));
    int cy = min(7, max(0, (int)(y * 8.f)));
    int cz = min(7, max(0, (int)(z * 8.f)));
    return spread3(cx) | (spread3(cy) << 1) | (spread3(cz) << 2);
}

__global__ void __launch_bounds__(1024, 1) fps_kernel(
    const float* __restrict__ xyz, const int* __restrict__ fgmask,
    int* __restrict__ fpsPid, int* __restrict__ idxInt, float* __restrict__ idxOutF)
{
    extern __shared__ float sh[];
    float* xs = sh;               // 14336
    float* ys = sh + 14336;
    float* zs = sh + 28672;
    __shared__ int hist[512];
    __shared__ uint2 warpRes[2][32];
    __shared__ float boxes[32][2][6];   // [warp][half][xl,xh,yl,yh,zl,zh]

    const int blk = blockIdx.x, b = blk >> 1, isFg = !(blk & 1);
    const float* X = xyz + (size_t)b * NPTS * 3;
    const int* Mk = fgmask + b * NPTS;
    int* pidbuf = fpsPid + blk * 14336;
    const int tid = threadIdx.x, lane = tid & 31, wid = tid >> 5;
    const int cnt = isFg ? TOPK_K : (NPTS - TOPK_K);   // 2048 / 14336
    const int nwActive = isFg ? 5 : 32;
    const int padded = nwActive * WSLOT;               // 2240 / 14336
    const int nbar = nwActive * 32;

    if (tid < 512) hist[tid] = 0;
    __syncthreads();
    for (int i = tid; i < NPTS; i += 1024) {
        int m = Mk[i]; if (!isFg) m = !m;
        if (m) atomicAdd(&hist[cellOf(X[i*3], X[i*3+1], X[i*3+2])], 1);
    }
    __syncthreads();
    {
        int* sa = (int*)xs;
        int* sb = sa + 512;
        if (tid < 512) sa[tid] = hist[tid];
        __syncthreads();
        for (int off = 1; off < 512; off <<= 1) {
            int v = 0;
            if (tid < 512) v = sa[tid] + (tid >= off ? sa[tid - off] : 0);
            __syncthreads();
            if (tid < 512) sb[tid] = v;
            int* tp = sa; sa = sb; sb = tp;
            __syncthreads();
        }
        int excl = 0;
        if (tid < 512) excl = sa[tid] - hist[tid];
        __syncthreads();
        if (tid < 512) hist[tid] = excl;
    }
    __syncthreads();
    for (int i = tid; i < NPTS; i += 1024) {
        int m = Mk[i]; if (!isFg) m = !m;
        if (m) {
            float x = X[i*3], y = X[i*3+1], z = X[i*3+2];
            int pos = atomicAdd(&hist[cellOf(x, y, z)], 1);
            xs[pos] = x; ys[pos] = y; zs[pos] = z;
            pidbuf[pos] = i;
        }
    }
    __syncthreads();
    for (int i = cnt + tid; i < padded; i += 1024) {
        xs[i] = xs[cnt-1]; ys[i] = ys[cnt-1]; zs[i] = zs[cnt-1];
        pidbuf[i] = pidbuf[cnt-1];
    }
    __syncthreads();

    if (wid >= nwActive) {
        if (lane == 0) {
            warpRes[0][wid] = make_uint2(0u, 0xFFFFFFFFu);
            warpRes[1][wid] = make_uint2(0u, 0xFFFFFFFFu);
        }
        return;
    }

    const int wbase = wid * WSLOT;
    const float2* xs2 = (const float2*)xs;
    const float2* ys2 = (const float2*)ys;
    const float2* zs2 = (const float2*)zs;
    const int pbase = (wbase >> 1) + lane;

    float mindL[NPAIR], mindH[NPAIR];
    uint32_t pkL[NPAIR], pkH[NPAIR];
    // per-half box build
#pragma unroll
    for (int h = 0; h < 2; h++) {
        float cxl = 1e9f, cxh = -1e9f, cyl = 1e9f, cyh = -1e9f, czl = 1e9f, czh = -1e9f;
        const int p0 = h ? HA : 0, p1 = h ? NPAIR : HA;
        for (int p = p0; p < p1; p++) {
            float2 xp = xs2[pbase + p * 32];
            float2 yp = ys2[pbase + p * 32];
            float2 zp = zs2[pbase + p * 32];
            cxl = fminf(cxl, fminf(xp.x, xp.y)); cxh = fmaxf(cxh, fmaxf(xp.x, xp.y));
            cyl = fminf(cyl, fminf(yp.x, yp.y)); cyh = fmaxf(cyh, fmaxf(yp.x, yp.y));
            czl = fminf(czl, fminf(zp.x, zp.y)); czh = fmaxf(czh, fmaxf(zp.x, zp.y));
        }
#pragma unroll
        for (int off = 16; off; off >>= 1) {
            cxl = fminf(cxl, __shfl_xor_sync(0xFFFFFFFFu, cxl, off));
            cxh = fmaxf(cxh, __shfl_xor_sync(0xFFFFFFFFu, cxh, off));
            cyl = fminf(cyl, __shfl_xor_sync(0xFFFFFFFFu, cyl, off));
            cyh = fmaxf(cyh, __shfl_xor_sync(0xFFFFFFFFu, cyh, off));
            czl = fminf(czl, __shfl_xor_sync(0xFFFFFFFFu, czl, off));
            czh = fmaxf(czh, __shfl_xor_sync(0xFFFFFFFFu, czh, off));
        }
        if (lane == 0) {
            boxes[wid][h][0] = cxl; boxes[wid][h][1] = cxh;
            boxes[wid][h][2] = cyl; boxes[wid][h][3] = cyh;
            boxes[wid][h][4] = czl; boxes[wid][h][5] = czh;
        }
    }
#pragma unroll
    for (int p = 0; p < NPAIR; p++) {
        int s0 = wbase + (p * 32 + lane) * 2;
        int2 pp = *(const int2*)&pidbuf[s0];
        pkL[p] = ((uint32_t)pp.x << 14) | (uint32_t)s0;
        pkH[p] = ((uint32_t)pp.y << 14) | (uint32_t)(s0 + 1);
        mindL[p] = 1e10f; mindH[p] = 1e10f;
    }
    __syncwarp();
    float bvA = 1e10f, bvB = 1e10f;
    uint32_t biA = 0xFFFFFFFFu, biB = 0xFFFFFFFFu;
#pragma unroll
    for (int p = 0; p < HA; p++) biA = min(biA, min(pkL[p], pkH[p]));
#pragma unroll
    for (int p = HA; p < NPAIR; p++) biB = min(biB, min(pkL[p], pkH[p]));

    const int outBase = b * NPOINT + (isFg ? 0 : FG_NS);
    for (int it = 0; it < FG_NS; it++) {
        const int s = it & 1;
        // candidate = lexicographic max over both halves
        float bv = fmaxf(bvA, bvB);
        uint32_t bi = 0xFFFFFFFFu;
        bi = (bvA == bv) ? min(bi, biA) : bi;
        bi = (bvB == bv) ? min(bi, biB) : bi;
        uint32_t key = __float_as_uint(bv);
        uint32_t kmax = __reduce_max_sync(0xFFFFFFFFu, key);
        uint32_t cmin = __reduce_min_sync(0xFFFFFFFFu, (key == kmax) ? bi : 0xFFFFFFFFu);
        if (lane == 0) warpRes[s][wid] = make_uint2(kmax, cmin);
        asm volatile("bar.sync 1, %0;" :: "r"(nbar) : "memory");
        uint2 e = warpRes[s][lane];
        uint32_t k2 = __reduce_max_sync(0xFFFFFFFFu, e.x);
        uint32_t c2 = __reduce_min_sync(0xFFFFFFFFu, (e.x == k2) ? e.y : 0xFFFFFFFFu);
        int slot = (int)(c2 & 0x3FFFu);
        if (wid == 0 && lane == 0) {
            int pid = (int)(c2 >> 14);
            idxInt[outBase + it] = pid;
            idxOutF[outBase + it] = (float)pid;
        }
        float sx = xs[slot], sy = ys[slot], sz = zs[slot];   // broadcast LDS
        unsigned long long nsx = pk2(-sx, -sx);
        unsigned long long nsy = pk2(-sy, -sy);
        unsigned long long nsz = pk2(-sz, -sz);
        // half A
        {
            const float* bx = boxes[wid][0];
            float dxc = fmaxf(fmaxf(__fsub_rn(bx[0], sx), __fsub_rn(sx, bx[1])), 0.f);
            float dyc = fmaxf(fmaxf(__fsub_rn(bx[2], sy), __fsub_rn(sy, bx[3])), 0.f);
            float dzc = fmaxf(fmaxf(__fsub_rn(bx[4], sz), __fsub_rn(sz, bx[5])), 0.f);
            float LBm = (dxc * dxc + dyc * dyc + dzc * dzc) * 0.999f - 1e-6f;
            if (!__all_sync(0xFFFFFFFFu, LBm >= bvA)) {
                float nbv = 0.f;
#pragma unroll
                for (int p = 0; p < HA; p++) {
                    float2 xp = xs2[pbase + p * 32];
                    float2 yp = ys2[pbase + p * 32];
                    float2 zp = zs2[pbase + p * 32];
                    unsigned long long dx2 = add2(pk2(xp.x, xp.y), nsx);
                    unsigned long long dy2 = add2(pk2(yp.x, yp.y), nsy);
                    unsigned long long dz2 = add2(pk2(zp.x, zp.y), nsz);
                    unsigned long long d2 = add2(add2(mul2(dx2, dx2), mul2(dy2, dy2)),
                                                 mul2(dz2, dz2));
                    float d0, d1;
                    upk2(d2, d0, d1);
                    mindL[p] = fminf(mindL[p], d0);
                    mindH[p] = fminf(mindH[p], d1);
                    nbv = fmaxf(nbv, fmaxf(mindL[p], mindH[p]));
                }
                uint32_t nbi = 0xFFFFFFFFu;
#pragma unroll
                for (int p = 0; p < HA; p++) {
                    nbi = (mindL[p] == nbv) ? min(nbi, pkL[p]) : nbi;
                    nbi = (mindH[p] == nbv) ? min(nbi, pkH[p]) : nbi;
                }
                bvA = nbv;
                biA = nbi;
            }
        }
        // half B
        {
            const float* bx = boxes[wid][1];
            float dxc = fmaxf(fmaxf(__fsub_rn(bx[0], sx), __fsub_rn(sx, bx[1])), 0.f);
            float dyc = fmaxf(fmaxf(__fsub_rn(bx[2], sy), __fsub_rn(sy, bx[3])), 0.f);
            float dzc = fmaxf(fmaxf(__fsub_rn(bx[4], sz), __fsub_rn(sz, bx[5])), 0.f);
            float LBm = (dxc * dxc + dyc * dyc + dzc * dzc) * 0.999f - 1e-6f;
            if (!__all_sync(0xFFFFFFFFu, LBm >= bvB)) {
                float nbv = 0.f;
#pragma unroll
                for (int p = HA; p < NPAIR; p++) {
                    float2 xp = xs2[pbase + p * 32];
                    float2 yp = ys2[pbase + p * 32];
                    float2 zp = zs2[pbase + p * 32];
                    unsigned long long dx2 = add2(pk2(xp.x, xp.y), nsx);
                    unsigned long long dy2 = add2(pk2(yp.x, yp.y), nsy);
                    unsigned long long dz2 = add2(pk2(zp.x, zp.y), nsz);
                    unsigned long long d2 = add2(add2(mul2(dx2, dx2), mul2(dy2, dy2)),
                                                 mul2(dz2, dz2));
                    float d0, d1;
                    upk2(d2, d0, d1);
                    mindL[p] = fminf(mindL[p], d0);
                    mindH[p] = fminf(mindH[p], d1);
                    nbv = fmaxf(nbv, fmaxf(mindL[p], mindH[p]));
                }
                uint32_t nbi = 0xFFFFFFFFu;
#pragma unroll
                for (int p = HA; p < NPAIR; p++) {
                    nbi = (mindL[p] == nbv) ? min(nbi, pkL[p]) : nbi;
                    nbi = (mindH[p] == nbv) ? min(nbi, pkH[p]) : nbi;
                }
                bvB = nbv;
                biB = nbi;
            }
        }
    }
}

// ---------------------------------------------------------------------------
// ball query + fused centroid gather: one warp per query
// ---------------------------------------------------------------------------
__global__ void ballq_kernel(const float* __restrict__ xyz, const int* __restrict__ idxInt,
                             float* __restrict__ newxyz, float* __restrict__ outXyz,
                             int* __restrict__ ballIdx)
{
    __shared__ int lists[8][32];
    int warp = threadIdx.x >> 5, lane = threadIdx.x & 31;
    int q = blockIdx.x * 8 + warp;
    int b = q >> 10;
    const float* X = xyz + (size_t)b * NPTS * 3;
    int sel = idxInt[q];
    float qx = X[sel * 3], qy = X[sel * 3 + 1], qz = X[sel * 3 + 2];
    if (lane < 3) {
        float v = X[sel * 3 + lane];
        newxyz[q * 3 + lane] = v;
        outXyz[q * 3 + lane] = v;
    }
    const float R2 = (float)(0.3 * 0.3);
    int cnt = 0;
    for (int chunk = 0; chunk < NPTS / 32; chunk++) {
        int p = chunk * 32 + lane;
        float dx = __fsub_rn(qx, X[p * 3 + 0]);
        float dy = __fsub_rn(qy, X[p * 3 + 1]);
        float dz = __fsub_rn(qz, X[p * 3 + 2]);
        float d2 = __fadd_rn(__fadd_rn(__fmul_rn(dx, dx), __fmul_rn(dy, dy)),
                             __fmul_rn(dz, dz));
        bool in = (d2 <= R2);
        unsigned m = __ballot_sync(0xFFFFFFFFu, in);
        if (m) {
            int pos = cnt + __popc(m & ((1u << lane) - 1u));
            if (in && pos < 32) lists[warp][pos] = p;
            cnt += __popc(m);
            if (cnt >= 32) break;
        }
    }
    __syncwarp();
    int c = cnt < 32 ? cnt : 32;
    int v = (lane < c) ? lists[warp][lane] : lists[warp][0];
    ballIdx[q * 32 + lane] = v;
}

// ---------------------------------------------------------------------------
// final maxpool (BN3 finalize fused)
// ---------------------------------------------------------------------------
__global__ void maxpool_final(const float* __restrict__ pmax, const float* __restrict__ pmin,
                              const float* __restrict__ g3, const float* __restrict__ b3,
                              float* __restrict__ outFeat)
{
    __shared__ float sa_, sc_;
    int t = blockIdx.x * blockDim.x + threadIdx.x;   // 1048576
    int m = t >> 12;
    if (threadIdx.x == 0) bn_affine(3, m, (double)NCOLS2D, g3, b3, sa_, sc_);
    __syncthreads();
    float a = sa_, c = sc_;
    int cent = t & 4095;
    float y = (a >= 0.f) ? pmax[t] : pmin[t];
    float v = fmaxf(fmaf(a, y, c), 0.f);
    int b = cent >> 10, s = cent & 1023;
    outFeat[(((size_t)b * 256 + m) << 10) + s] = v;
}

// ---------------------------------------------------------------------------
extern "C" void kernel_launch(void* const* d_in, const int* in_sizes, int n_in,
                              void* d_out, int out_size)
{
    const float* xyz      = (const float*)d_in[0];
    const float* features = (const float*)d_in[1];
    const float* w1  = (const float*)d_in[2];
    const float* g1  = (const float*)d_in[3];
    const float* b1  = (const float*)d_in[4];
    const float* w2  = (const float*)d_in[5];
    const float* g2  = (const float*)d_in[6];
    const float* b2  = (const float*)d_in[7];
    const float* w3  = (const float*)d_in[8];
    const float* g3  = (const float*)d_in[9];
    const float* b3  = (const float*)d_in[10];
    const float* fw1 = (const float*)d_in[11];
    const float* fg1 = (const float*)d_in[12];
    const float* fb1 = (const float*)d_in[13];
    const float* fw2 = (const float*)d_in[14];
    const float* fbias2 = (const float*)d_in[15];

    float* out = (float*)d_out;
    float* outXyz    = out + OFS_XYZ;
    float* outFeat   = out + OFS_FEAT;
    float* outIdx    = out + OFS_IDX;
    float* outScores = out + OFS_SCORES;

    float* scr = nullptr;
    cudaGetSymbolAddress((void**)&scr, g_scratch);
    float* y1d    = scr + O_Y1D;
    float* y1T    = scr + O_Y1T;
    float* y2T    = scr + O_Y2T;
    float* p3max  = scr + O_P3MAX;
    float* p3min  = scr + O_P3MIN;
    float* margin = scr + O_MARGIN;
    float* newxyz = scr + O_NEWXYZ;
    float* wpad   = scr + O_WPAD;
    float* featT  = scr + O_FEATT;
    int* fgmask   = (int*)(scr + O_FGMASK);
    int* idxInt   = (int*)(scr + O_INDICES);
    int* ballIdx  = (int*)(scr + O_BALL);
    int* fpsPid   = (int*)(scr + O_FPSPID);

    gemm_fused<4><<<dim3(NCOLS1D / 128, 1), 256>>>(fw1, features, y1d, 128, NCOLS1D, 0);
    maskhead_kernel<<<NCOLS1D / 256, 256>>>(y1d, fg1, fb1, fw2, fbias2, outScores, margin);
    select_kernel<<<4, 256>>>(margin, fgmask);

    cudaFuncSetAttribute(fps_kernel, cudaFuncAttributeMaxDynamicSharedMemorySize, 14336 * 12);
    fps_kernel<<<8, 1024, 14336 * 12>>>(xyz, fgmask, fpsPid, idxInt, outIdx);

    prep_kernel<<<80, 256>>>(w1, wpad);
    transpose_kernel<<<dim3(NPTS / 32, CIN / 32, BATCH), dim3(32, 8)>>>(features, featT);
    ballq_kernel<<<NPOINT * BATCH / 8, 256>>>(xyz, idxInt, newxyz, outXyz, ballIdx);

    // conv1: NT=128, B gathered on the fly; K permuted [feat|xyz|pad]
    {
        auto k = conv_mma<KX1, 128, -1, 1, 0, 1>;
        size_t sm = (size_t)(128 + 128) * (KX1 + 4) * 4;
        cudaFuncSetAttribute(k, cudaFuncAttributeMaxDynamicSharedMemorySize, (int)sm);
        k<<<dim3(NCOLS2D / 128, 1), 256, sm>>>(wpad, featT, y1T, nullptr, nullptr,
                                               nullptr, nullptr, ballIdx, xyz, newxyz);
    }
    // conv2: NT=64 (occ 2), BN1+relu on B-load
    {
        auto k = conv_mma<128, 64, 1, 2, 0, 0>;
        size_t sm = (size_t)(128 + 64) * 132 * 4;
        cudaFuncSetAttribute(k, cudaFuncAttributeMaxDynamicSharedMemorySize, (int)sm);
        k<<<dim3(NCOLS2D / 64, 1), 256, sm>>>(w2, y1T, y2T, nullptr, nullptr, g1, b1,
                                              nullptr, nullptr, nullptr);
    }
    // conv3: NT=64 (occ 2), M=256 via grid.y=2, BN2+relu on B-load, pool fused
    {
        auto k = conv_mma<128, 64, 2, 3, 1, 0>;
        size_t sm = (size_t)(128 + 64) * 132 * 4;
        cudaFuncSetAttribute(k, cudaFuncAttributeMaxDynamicSharedMemorySize, (int)sm);
        k<<<dim3(NCOLS2D / 64, 2), 256, sm>>>(w3, y2T, nullptr, p3max, p3min, g2, b2,
                                              nullptr, nullptr, nullptr);
    }
    maxpool_final<<<(256 * 4096) / 256, 256>>>(p3max, p3min, g3, b3, outFeat);
}

// round 15
// speedup vs baseline: 1.0081x; 1.0081x over previous
#include <cuda_runtime.h>
#include <cuda_bf16.h>
#include <cstdint>

#define BATCH   4
#define NPTS    16384
#define CIN     128
#define NPOINT  1024
#define FG_NS   512
#define TOPK_K  2048
#define NCOLS2D 131072
#define NCOLS1D 65536
#define KX1     160

#define OFS_XYZ    0
#define OFS_FEAT   12288
#define OFS_IDX    (12288 + 1048576)
#define OFS_SCORES (12288 + 1048576 + 4096)

#define O_Y1D     0ull
#define O_Y1T     25165824ull
#define O_Y2T     41943040ull
#define O_P3MAX   58720256ull
#define O_P3MIN   59768832ull
#define O_MARGIN  60817408ull
#define O_NEWXYZ  60882944ull
#define O_FGMASK  60895232ull
#define O_INDICES 60960768ull
#define O_BALL    60964864ull
#define O_WPAD    61095936ull
#define O_FEATT   61116416ull
#define O_FPSPID  69505024ull
#define SCRATCH_FLOATS 69619712ull

__device__ float g_scratch[SCRATCH_FLOATS];
__device__ double g_sum[4][256];
__device__ double g_sumsq[4][256];

// ---------------------------------------------------------------------------
__device__ __forceinline__ float tf32r(float x) {
    uint32_t u;
    asm("cvt.rna.tf32.f32 %0, %1;" : "=r"(u) : "f"(x));
    return __uint_as_float(u);
}
__device__ __forceinline__ void mma_tf32(float* c, uint32_t a0, uint32_t a1,
                                         uint32_t a2, uint32_t a3,
                                         uint32_t b0, uint32_t b1) {
    asm("mma.sync.aligned.m16n8k8.row.col.f32.tf32.tf32.f32 "
        "{%0,%1,%2,%3},{%4,%5,%6,%7},{%8,%9},{%0,%1,%2,%3};"
        : "+f"(c[0]), "+f"(c[1]), "+f"(c[2]), "+f"(c[3])
        : "r"(a0), "r"(a1), "r"(a2), "r"(a3), "r"(b0), "r"(b1));
}
__device__ __forceinline__ void bn_affine(int layer, int m, double cnt,
                                          const float* g, const float* beta,
                                          float& a, float& c) {
    double mu = g_sum[layer][m] / cnt;
    double var = g_sumsq[layer][m] / cnt - mu * mu;
    a = g[m] * rsqrtf((float)var + 1e-5f);
    c = beta[m] - (float)mu * a;
}
// packed f32x2 helpers (per-element .rn == scalar rn)
__device__ __forceinline__ unsigned long long pk2(float lo, float hi) {
    unsigned long long r;
    asm("mov.b64 %0, {%1, %2};" : "=l"(r) : "f"(lo), "f"(hi));
    return r;
}
__device__ __forceinline__ unsigned long long add2(unsigned long long a,
                                                   unsigned long long b) {
    unsigned long long d;
    asm("add.rn.f32x2 %0, %1, %2;" : "=l"(d) : "l"(a), "l"(b));
    return d;
}
__device__ __forceinline__ unsigned long long mul2(unsigned long long a,
                                                   unsigned long long b) {
    unsigned long long d;
    asm("mul.rn.f32x2 %0, %1, %2;" : "=l"(d) : "l"(a), "l"(b));
    return d;
}
__device__ __forceinline__ unsigned long long fma2(unsigned long long a,
                                                   unsigned long long b,
                                                   unsigned long long c) {
    unsigned long long d;
    asm("fma.rn.f32x2 %0, %1, %2, %3;" : "=l"(d) : "l"(a), "l"(b), "l"(c));
    return d;
}
__device__ __forceinline__ void upk2(unsigned long long v, float& lo, float& hi) {
    asm("mov.b64 {%0, %1}, %2;" : "=f"(lo), "=f"(hi) : "l"(v));
}

// ---------------------------------------------------------------------------
// prep: zero stats + build PERMUTED padded w1 ([feat(128) | xyz(3) | pad])
// ---------------------------------------------------------------------------
__global__ void prep_kernel(const float* __restrict__ w1, float* __restrict__ wpad) {
    int t = blockIdx.x * blockDim.x + threadIdx.x;   // 20480 = 128*160
    if (blockIdx.x == 0) {
        double* s  = &g_sum[0][0];
        double* s2 = &g_sumsq[0][0];
        for (int i = threadIdx.x; i < 4 * 256; i += 256) { s[i] = 0.0; s2[i] = 0.0; }
    }
    int o = t / KX1, c = t % KX1;
    float v = 0.f;
    if (c < 128)       v = w1[o * 131 + c + 3];
    else if (c < 131)  v = w1[o * 131 + c - 128];
    wpad[t] = v;
}

__global__ void transpose_kernel(const float* __restrict__ features,
                                 float* __restrict__ featT)
{
    __shared__ float tile[32][33];
    int b = blockIdx.z;
    int n0 = blockIdx.x * 32, c0 = blockIdx.y * 32;
    int x = threadIdx.x, y = threadIdx.y;
#pragma unroll
    for (int k = 0; k < 32; k += 8)
        tile[y + k][x] = features[((size_t)b * CIN + c0 + y + k) * NPTS + n0 + x];
    __syncthreads();
#pragma unroll
    for (int k = 0; k < 32; k += 8)
        featT[((size_t)b * NPTS + n0 + y + k) * CIN + c0 + x] = tile[x][y + k];
}

// ---------------------------------------------------------------------------
// tf32 mma.sync conv GEMM. Tile = 128 rows x NT cols.
// ---------------------------------------------------------------------------
template<int KE, int NT, int AFF, int STATS, int POOL, int GB>
__global__ void __launch_bounds__(256, (NT == 64) ? 2 : 1) conv_mma(
    const float* __restrict__ W, const float* __restrict__ Xin,
    float* __restrict__ Yout, float* __restrict__ poolMax, float* __restrict__ poolMin,
    const float* __restrict__ gPrev, const float* __restrict__ bPrev,
    const int* __restrict__ ballIdx, const float* __restrict__ xyzIn,
    const float* __restrict__ newxyz)
{
    constexpr int LDK = KE + 4;
    constexpr int NWN = (NT == 128) ? 4 : 2;
    constexpr int MA  = (NT == 128) ? 4 : 2;
    extern __shared__ float sm[];
    float* As = sm;                     // [128][LDK]
    float* Bs = sm + 128 * LDK;         // [NT][LDK]
    __shared__ __align__(16) float affA[128];
    __shared__ __align__(16) float affC[128];
    const int tid = threadIdx.x;
    const int wid = tid >> 5, lane = tid & 31;
    const int g = lane >> 2, t = lane & 3;
    const int wm = wid / NWN, wn = wid % NWN;
    const int rowBase = blockIdx.y * 128;
    const int colBase = blockIdx.x * NT;

    if (AFF >= 0) {
        if (tid < 128)
            bn_affine(AFF, tid, (double)NCOLS2D, gPrev, bPrev, affA[tid], affC[tid]);
        __syncthreads();
    }
    for (int i = tid; i < 128 * (KE / 4); i += 256) {
        int r = i / (KE / 4), k = (i % (KE / 4)) * 4;
        float4 v = *(const float4*)(W + (size_t)(rowBase + r) * KE + k);
        As[r * LDK + k + 0] = tf32r(v.x);
        As[r * LDK + k + 1] = tf32r(v.y);
        As[r * LDK + k + 2] = tf32r(v.z);
        As[r * LDK + k + 3] = tf32r(v.w);
    }
    for (int i = tid; i < NT * (KE / 4); i += 256) {
        int r = i / (KE / 4), k = (i % (KE / 4)) * 4;
        float4 v;
        if (GB) {
            int col = colBase + r;
            int idx = ballIdx[col];
            int bb = col >> 15;
            if (k < 128) {
                v = *(const float4*)(Xin + ((size_t)(bb * NPTS + idx)) * 128 + k);
            } else if (k == 128) {
                int q = col >> 5;
                const float* xp = xyzIn + ((size_t)bb * NPTS + idx) * 3;
                v.x = __fsub_rn(xp[0], newxyz[q * 3 + 0]);
                v.y = __fsub_rn(xp[1], newxyz[q * 3 + 1]);
                v.z = __fsub_rn(xp[2], newxyz[q * 3 + 2]);
                v.w = 0.f;
            } else {
                v = make_float4(0.f, 0.f, 0.f, 0.f);
            }
        } else {
            v = *(const float4*)(Xin + (size_t)(colBase + r) * KE + k);
            if (AFF >= 0) {
                float4 av = *(const float4*)&affA[k];
                float4 cv = *(const float4*)&affC[k];
                v.x = fmaxf(fmaf(av.x, v.x, cv.x), 0.f);
                v.y = fmaxf(fmaf(av.y, v.y, cv.y), 0.f);
                v.z = fmaxf(fmaf(av.z, v.z, cv.z), 0.f);
                v.w = fmaxf(fmaf(av.w, v.w, cv.w), 0.f);
            }
        }
        Bs[r * LDK + k + 0] = tf32r(v.x);
        Bs[r * LDK + k + 1] = tf32r(v.y);
        Bs[r * LDK + k + 2] = tf32r(v.z);
        Bs[r * LDK + k + 3] = tf32r(v.w);
    }
    __syncthreads();

    float acc[MA][4][4];
#pragma unroll
    for (int i = 0; i < MA; i++)
#pragma unroll
        for (int j = 0; j < 4; j++)
#pragma unroll
            for (int c = 0; c < 4; c++) acc[i][j][c] = 0.f;

    const float* Arow0 = As + (size_t)(wm * (MA * 16) + g) * LDK + t;
    const float* Arow8 = Arow0 + 8 * LDK;
    const float* Bcol0 = Bs + (size_t)(wn * 32 + g) * LDK + t;

#pragma unroll 4
    for (int ks = 0; ks < KE / 8; ks++) {
        const int k0 = ks * 8;
        uint32_t a[MA][4], b[4][2];
#pragma unroll
        for (int ma = 0; ma < MA; ma++) {
            const float* p0 = Arow0 + ma * 16 * LDK + k0;
            const float* p8 = Arow8 + ma * 16 * LDK + k0;
            a[ma][0] = __float_as_uint(p0[0]);
            a[ma][1] = __float_as_uint(p8[0]);
            a[ma][2] = __float_as_uint(p0[4]);
            a[ma][3] = __float_as_uint(p8[4]);
        }
#pragma unroll
        for (int nb = 0; nb < 4; nb++) {
            const float* pb = Bcol0 + nb * 8 * LDK + k0;
            b[nb][0] = __float_as_uint(pb[0]);
            b[nb][1] = __float_as_uint(pb[4]);
        }
#pragma unroll
        for (int ma = 0; ma < MA; ma++)
#pragma unroll
            for (int nb = 0; nb < 4; nb++)
                mma_tf32(acc[ma][nb], a[ma][0], a[ma][1], a[ma][2], a[ma][3],
                         b[nb][0], b[nb][1]);
    }

#pragma unroll
    for (int ma = 0; ma < MA; ma++) {
        int r0 = wm * (MA * 16) + ma * 16 + g;
        float s0 = 0.f, q0 = 0.f, s1 = 0.f, q1 = 0.f;
        float mx0 = -1e30f, mn0 = 1e30f, mx1 = -1e30f, mn1 = 1e30f;
#pragma unroll
        for (int nb = 0; nb < 4; nb++) {
            float c0 = acc[ma][nb][0], c1 = acc[ma][nb][1];
            float c2 = acc[ma][nb][2], c3 = acc[ma][nb][3];
            s0 += c0 + c1; q0 = fmaf(c0, c0, fmaf(c1, c1, q0));
            s1 += c2 + c3; q1 = fmaf(c2, c2, fmaf(c3, c3, q1));
            if (POOL) {
                mx0 = fmaxf(mx0, fmaxf(c0, c1)); mn0 = fminf(mn0, fminf(c0, c1));
                mx1 = fmaxf(mx1, fmaxf(c2, c3)); mn1 = fminf(mn1, fminf(c2, c3));
            }
        }
#pragma unroll
        for (int off = 1; off < 4; off <<= 1) {
            s0 += __shfl_xor_sync(0xFFFFFFFFu, s0, off);
            q0 += __shfl_xor_sync(0xFFFFFFFFu, q0, off);
            s1 += __shfl_xor_sync(0xFFFFFFFFu, s1, off);
            q1 += __shfl_xor_sync(0xFFFFFFFFu, q1, off);
            if (POOL) {
                mx0 = fmaxf(mx0, __shfl_xor_sync(0xFFFFFFFFu, mx0, off));
                mn0 = fminf(mn0, __shfl_xor_sync(0xFFFFFFFFu, mn0, off));
                mx1 = fmaxf(mx1, __shfl_xor_sync(0xFFFFFFFFu, mx1, off));
                mn1 = fminf(mn1, __shfl_xor_sync(0xFFFFFFFFu, mn1, off));
            }
        }
        if (t == 0) {
            atomicAdd(&g_sum[STATS][rowBase + r0], (double)s0);
            atomicAdd(&g_sumsq[STATS][rowBase + r0], (double)q0);
            atomicAdd(&g_sum[STATS][rowBase + r0 + 8], (double)s1);
            atomicAdd(&g_sumsq[STATS][rowBase + r0 + 8], (double)q1);
            if (POOL) {
                int cent = (colBase >> 5) + wn;
                poolMax[(size_t)(rowBase + r0) * 4096 + cent] = mx0;
                poolMin[(size_t)(rowBase + r0) * 4096 + cent] = mn0;
                poolMax[(size_t)(rowBase + r0 + 8) * 4096 + cent] = mx1;
                poolMin[(size_t)(rowBase + r0 + 8) * 4096 + cent] = mn1;
            }
        }
    }

    if (!POOL) {
        __syncthreads();
        float* Ct = As;   // [NT cols][132]
#pragma unroll
        for (int ma = 0; ma < MA; ma++) {
            int r0 = wm * (MA * 16) + ma * 16 + g;
#pragma unroll
            for (int nb = 0; nb < 4; nb++) {
                int col0 = wn * 32 + nb * 8 + 2 * t;
                Ct[col0 * 132 + r0]           = acc[ma][nb][0];
                Ct[(col0 + 1) * 132 + r0]     = acc[ma][nb][1];
                Ct[col0 * 132 + r0 + 8]       = acc[ma][nb][2];
                Ct[(col0 + 1) * 132 + r0 + 8] = acc[ma][nb][3];
            }
        }
        __syncthreads();
        for (int i = tid; i < NT * 32; i += 256) {
            int col = i >> 5;
            int r4 = (i & 31) * 4;
            float4 v = *(float4*)&Ct[col * 132 + r4];
            *(float4*)(Yout + (size_t)(colBase + col) * 128 + r4) = v;
        }
    }
}

// ---------------------------------------------------------------------------
// SIMT SGEMM for mask-head conv — fp32 exact via packed fma.rn.f32x2
// ---------------------------------------------------------------------------
template<int RT>
__global__ void __launch_bounds__(256, 2) gemm_fused(
    const float* __restrict__ A, const float* __restrict__ B, float* __restrict__ C,
    int K, int Ncols, int statsLayer)
{
    constexpr int TM = RT * 16;
    __shared__ float As[2][16][TM + 4];
    __shared__ __align__(16) float Bs[2][16][128];
    const int tid = threadIdx.x;
    const int tx = tid & 15, ty = tid >> 4;
    const int rowBase = blockIdx.y * TM;
    const int colBase = blockIdx.x * 128;

    unsigned long long acc2[RT][4];
#pragma unroll
    for (int i = 0; i < RT; i++)
#pragma unroll
        for (int j = 0; j < 4; j++) acc2[i][j] = 0ull;

    const int ktiles = K >> 4;
    {
#pragma unroll
        for (int l = 0; l < RT; l++) {
            int i = l * 256 + tid;
            int r = i >> 4, kk = i & 15;
            As[0][kk][r] = A[(rowBase + r) * K + kk];
        }
#pragma unroll
        for (int l = 0; l < 2; l++) {
            int i = l * 256 + tid;
            int kk = i >> 5, c4 = i & 31;
            int gc = colBase + c4 * 4;
            const float* src = B + (((size_t)(gc >> 14) * 128 + kk) << 14) + (gc & 16383);
            *(float4*)&Bs[0][kk][c4 * 4] = *(const float4*)src;
        }
    }
    __syncthreads();

    float pa[RT];
    float4 pb0, pb1;
    for (int kt = 0; kt < ktiles; kt++) {
        const int cur = kt & 1, nxt = cur ^ 1;
        const bool more = (kt + 1 < ktiles);
        if (more) {
            const int k0 = (kt + 1) << 4;
#pragma unroll
            for (int l = 0; l < RT; l++) {
                int i = l * 256 + tid;
                int r = i >> 4, kk = i & 15;
                pa[l] = A[(rowBase + r) * K + k0 + kk];
            }
#pragma unroll
            for (int l = 0; l < 2; l++) {
                int i = l * 256 + tid;
                int kk = i >> 5, c4 = i & 31;
                int gk = k0 + kk, gc = colBase + c4 * 4;
                const float* src = B + (((size_t)(gc >> 14) * 128 + gk) << 14) + (gc & 16383);
                float4 v = *(const float4*)src;
                if (l == 0) pb0 = v; else pb1 = v;
            }
        }
#pragma unroll
        for (int kk = 0; kk < 16; kk++) {
            const unsigned long long* rbp =
                (const unsigned long long*)&Bs[cur][kk][tx * 8];
            unsigned long long rb2[4];
#pragma unroll
            for (int j = 0; j < 4; j++) rb2[j] = rbp[j];
#pragma unroll
            for (int i = 0; i < RT; i++) {
                float av = As[cur][kk][ty * RT + i];
                unsigned long long ra2 = pk2(av, av);
#pragma unroll
                for (int j = 0; j < 4; j++)
                    acc2[i][j] = fma2(ra2, rb2[j], acc2[i][j]);
            }
        }
        if (more) {
#pragma unroll
            for (int l = 0; l < RT; l++) {
                int i = l * 256 + tid;
                int r = i >> 4, kk = i & 15;
                As[nxt][kk][r] = pa[l];
            }
            { int kk = tid >> 5, c4 = tid & 31; *(float4*)&Bs[nxt][kk][c4 * 4] = pb0; }
            { int i = 256 + tid; int kk = i >> 5, c4 = i & 31; *(float4*)&Bs[nxt][kk][c4 * 4] = pb1; }
        }
        __syncthreads();
    }
    float acc[RT][8];
#pragma unroll
    for (int i = 0; i < RT; i++)
#pragma unroll
        for (int j = 0; j < 4; j++)
            upk2(acc2[i][j], acc[i][2 * j], acc[i][2 * j + 1]);
#pragma unroll
    for (int i = 0; i < RT; i++) {
        float* dst = C + (size_t)(rowBase + ty * RT + i) * Ncols + colBase + tx * 8;
        *(float4*)dst       = make_float4(acc[i][0], acc[i][1], acc[i][2], acc[i][3]);
        *(float4*)(dst + 4) = make_float4(acc[i][4], acc[i][5], acc[i][6], acc[i][7]);
    }
#pragma unroll
    for (int i = 0; i < RT; i++) {
        float s = 0.f, s2 = 0.f;
#pragma unroll
        for (int j = 0; j < 8; j++) { float v = acc[i][j]; s += v; s2 = fmaf(v, v, s2); }
#pragma unroll
        for (int off = 1; off < 16; off <<= 1) {
            s  += __shfl_xor_sync(0xFFFFFFFFu, s, off);
            s2 += __shfl_xor_sync(0xFFFFFFFFu, s2, off);
        }
        if (tx == 0) {
            int gr = rowBase + ty * RT + i;
            atomicAdd(&g_sum[statsLayer][gr], (double)s);
            atomicAdd(&g_sumsq[statsLayer][gr], (double)s2);
        }
    }
}

// ---------------------------------------------------------------------------
// mask head (BN0 finalize fused)
// ---------------------------------------------------------------------------
__global__ void maskhead_kernel(const float* __restrict__ y1d,
                                const float* __restrict__ fg1,
                                const float* __restrict__ fb1,
                                const float* __restrict__ fw2,
                                const float* __restrict__ fbias2,
                                float* __restrict__ outScores,
                                float* __restrict__ margin)
{
    __shared__ float affA[64], affC[64];
    if (threadIdx.x < 64)
        bn_affine(0, threadIdx.x, (double)NCOLS1D, fg1, fb1,
                  affA[threadIdx.x], affC[threadIdx.x]);
    __syncthreads();
    int col = blockIdx.x * blockDim.x + threadIdx.x;
    int b = col >> 14, n = col & 16383;
    float s0 = fbias2[0], s1 = fbias2[1];
#pragma unroll 4
    for (int c = 0; c < 64; c++) {
        float v = fmaxf(fmaf(affA[c], y1d[(size_t)c * NCOLS1D + col], affC[c]), 0.f);
        s0 = fmaf(fw2[c], v, s0);
        s1 = fmaf(fw2[64 + c], v, s1);
    }
    outScores[b * 32768 + n]         = s0;
    outScores[b * 32768 + 16384 + n] = s1;
    float mx = fmaxf(s0, s1);
    float e0 = expf(s0 - mx), e1 = expf(s1 - mx);
    margin[col] = (e1 - e0) / (e0 + e1);
}

// ---------------------------------------------------------------------------
// exact top-2048 per batch (radix select on 64-bit key)
// ---------------------------------------------------------------------------
__device__ __forceinline__ unsigned long long makeKey(float f, int i)
{
    unsigned u = __float_as_uint(f);
    u = (u & 0x80000000u) ? ~u : (u | 0x80000000u);
    return ((unsigned long long)u << 32) | (unsigned)(0xFFFFFFFFu - (unsigned)i);
}

__global__ void select_kernel(const float* __restrict__ margin, int* __restrict__ fgmask)
{
    __shared__ unsigned hist[256];
    __shared__ unsigned long long sprefix;
    __shared__ int skrem;
    int b = blockIdx.x, tid = threadIdx.x;
    const float* M = margin + b * NPTS;
    if (tid == 0) { sprefix = 0ull; skrem = TOPK_K; }
    __syncthreads();
    for (int pos = 56; pos >= 0; pos -= 8) {
        hist[tid] = 0;
        __syncthreads();
        unsigned long long pref = sprefix;
        for (int i = tid; i < NPTS; i += 256) {
            unsigned long long key = makeKey(M[i], i);
            bool act = (pos == 56) || ((key >> (pos + 8)) == (pref >> (pos + 8)));
            if (act) atomicAdd(&hist[(unsigned)(key >> pos) & 255u], 1u);
        }
        __syncthreads();
        if (tid == 0) {
            int k = skrem;
            int v = 255;
            while (v > 0 && (int)hist[v] < k) { k -= (int)hist[v]; v--; }
            skrem = k;
            sprefix = pref | ((unsigned long long)(unsigned)v << pos);
        }
        __syncthreads();
    }
    unsigned long long kth = sprefix;
    for (int i = tid; i < NPTS; i += 256)
        fgmask[b * NPTS + i] = (makeKey(M[i], i) >= kth) ? 1 : 0;
}

// ---------------------------------------------------------------------------
// masked FPS v6: 16^3 Morton sort (4096 cells -> tighter warp boxes),
// whole-warp box pruning, f32x2 packed math, one barrier/iter. Exact.
// ---------------------------------------------------------------------------
#define WSLOT 448
#define NPAIR 7
#define NCELL 4096

__device__ __forceinline__ int spread4(int v) {
    return (v & 1) | ((v & 2) << 2) | ((v & 4) << 4) | ((v & 8) << 6);
}
__device__ __forceinline__ int cellOf(float x, float y, float z) {
    int cx = min(15, max(0, (int)(x * 16.f)));
    int cy = min(15, max(0, (int)(y * 16.f)));
    int cz = min(15, max(0, (int)(z * 16.f)));
    return spread4(cx) | (spread4(cy) << 1) | (spread4(cz) << 2);
}

__global__ void __launch_bounds__(1024, 1) fps_kernel(
    const float* __restrict__ xyz, const int* __restrict__ fgmask,
    int* __restrict__ fpsPid, int* __restrict__ idxInt, float* __restrict__ idxOutF)
{
    extern __shared__ float sh[];
    float* xs = sh;               // 14336
    float* ys = sh + 14336;
    float* zs = sh + 28672;
    __shared__ int hist4[NCELL];          // 16 KB
    __shared__ uint2 warpRes[2][32];

    const int blk = blockIdx.x, b = blk >> 1, isFg = !(blk & 1);
    const float* X = xyz + (size_t)b * NPTS * 3;
    const int* Mk = fgmask + b * NPTS;
    int* pidbuf = fpsPid + blk * 14336;
    const int tid = threadIdx.x, lane = tid & 31, wid = tid >> 5;
    const int cnt = isFg ? TOPK_K : (NPTS - TOPK_K);   // 2048 / 14336
    const int nwActive = isFg ? 5 : 32;
    const int padded = nwActive * WSLOT;               // 2240 / 14336
    const int nbar = nwActive * 32;

    // Morton histogram (4096 cells)
    for (int i = tid; i < NCELL; i += 1024) hist4[i] = 0;
    __syncthreads();
    for (int i = tid; i < NPTS; i += 1024) {
        int m = Mk[i]; if (!isFg) m = !m;
        if (m) atomicAdd(&hist4[cellOf(X[i*3], X[i*3+1], X[i*3+2])], 1);
    }
    __syncthreads();
    // exclusive scan over 4096: 4 cells/thread serial + 1024-wide ping-pong scan
    {
        int* sa = (int*)xs;
        int* sb = sa + 1024;
        int base = tid * 4;
        int h0 = hist4[base], h1 = hist4[base + 1];
        int h2 = hist4[base + 2], h3 = hist4[base + 3];
        int tot = h0 + h1 + h2 + h3;
        sa[tid] = tot;
        __syncthreads();
        for (int off = 1; off < 1024; off <<= 1) {
            int v = sa[tid] + (tid >= off ? sa[tid - off] : 0);
            __syncthreads();
            sb[tid] = v;
            int* tp = sa; sa = sb; sb = tp;
            __syncthreads();
        }
        int excl = sa[tid] - tot;
        __syncthreads();
        hist4[base]     = excl;
        hist4[base + 1] = excl + h0;
        hist4[base + 2] = excl + h0 + h1;
        hist4[base + 3] = excl + h0 + h1 + h2;
    }
    __syncthreads();
    // scatter cell-sorted (SoA) + pid
    for (int i = tid; i < NPTS; i += 1024) {
        int m = Mk[i]; if (!isFg) m = !m;
        if (m) {
            float x = X[i*3], y = X[i*3+1], z = X[i*3+2];
            int pos = atomicAdd(&hist4[cellOf(x, y, z)], 1);
            xs[pos] = x; ys[pos] = y; zs[pos] = z;
            pidbuf[pos] = i;
        }
    }
    __syncthreads();
    // pads: duplicate last real point (same pid -> exact)
    for (int i = cnt + tid; i < padded; i += 1024) {
        xs[i] = xs[cnt-1]; ys[i] = ys[cnt-1]; zs[i] = zs[cnt-1];
        pidbuf[i] = pidbuf[cnt-1];
    }
    __syncthreads();

    if (wid >= nwActive) {
        if (lane == 0) {
            warpRes[0][wid] = make_uint2(0u, 0xFFFFFFFFu);
            warpRes[1][wid] = make_uint2(0u, 0xFFFFFFFFu);
        }
        return;
    }

    const int wbase = wid * WSLOT;
    const float2* xs2 = (const float2*)xs;
    const float2* ys2 = (const float2*)ys;
    const float2* zs2 = (const float2*)zs;
    const int pbase = (wbase >> 1) + lane;

    float mindL[NPAIR], mindH[NPAIR];
    uint32_t pkL[NPAIR], pkH[NPAIR];
    float bxl = 1e9f, bxh = -1e9f, byl = 1e9f, byh = -1e9f, bzl = 1e9f, bzh = -1e9f;
#pragma unroll
    for (int p = 0; p < NPAIR; p++) {
        int s0 = wbase + (p * 32 + lane) * 2;
        int2 pp = *(const int2*)&pidbuf[s0];
        pkL[p] = ((uint32_t)pp.x << 14) | (uint32_t)s0;
        pkH[p] = ((uint32_t)pp.y << 14) | (uint32_t)(s0 + 1);
        mindL[p] = 1e10f; mindH[p] = 1e10f;
        float2 xp = xs2[pbase + p * 32];
        float2 yp = ys2[pbase + p * 32];
        float2 zp = zs2[pbase + p * 32];
        bxl = fminf(bxl, fminf(xp.x, xp.y)); bxh = fmaxf(bxh, fmaxf(xp.x, xp.y));
        byl = fminf(byl, fminf(yp.x, yp.y)); byh = fmaxf(byh, fmaxf(yp.x, yp.y));
        bzl = fminf(bzl, fminf(zp.x, zp.y)); bzh = fmaxf(bzh, fmaxf(zp.x, zp.y));
    }
#pragma unroll
    for (int off = 16; off; off >>= 1) {
        bxl = fminf(bxl, __shfl_xor_sync(0xFFFFFFFFu, bxl, off));
        bxh = fmaxf(bxh, __shfl_xor_sync(0xFFFFFFFFu, bxh, off));
        byl = fminf(byl, __shfl_xor_sync(0xFFFFFFFFu, byl, off));
        byh = fmaxf(byh, __shfl_xor_sync(0xFFFFFFFFu, byh, off));
        bzl = fminf(bzl, __shfl_xor_sync(0xFFFFFFFFu, bzl, off));
        bzh = fmaxf(bzh, __shfl_xor_sync(0xFFFFFFFFu, bzh, off));
    }
    float bv = 1e10f;
    uint32_t bi = 0xFFFFFFFFu;
#pragma unroll
    for (int p = 0; p < NPAIR; p++) bi = min(bi, min(pkL[p], pkH[p]));

    const int outBase = b * NPOINT + (isFg ? 0 : FG_NS);
    for (int it = 0; it < FG_NS; it++) {
        const int s = it & 1;
        uint32_t key = __float_as_uint(bv);
        uint32_t kmax = __reduce_max_sync(0xFFFFFFFFu, key);
        uint32_t cmin = __reduce_min_sync(0xFFFFFFFFu, (key == kmax) ? bi : 0xFFFFFFFFu);
        if (lane == 0) warpRes[s][wid] = make_uint2(kmax, cmin);
        asm volatile("bar.sync 1, %0;" :: "r"(nbar) : "memory");
        // every active warp computes the global winner redundantly (parity-safe)
        uint2 e = warpRes[s][lane];
        uint32_t k2 = __reduce_max_sync(0xFFFFFFFFu, e.x);
        uint32_t c2 = __reduce_min_sync(0xFFFFFFFFu, (e.x == k2) ? e.y : 0xFFFFFFFFu);
        int slot = (int)(c2 & 0x3FFFu);
        if (wid == 0 && lane == 0) {
            int pid = (int)(c2 >> 14);
            idxInt[outBase + it] = pid;
            idxOutF[outBase + it] = (float)pid;
        }
        float sx = xs[slot], sy = ys[slot], sz = zs[slot];   // broadcast LDS
        float dxc = fmaxf(fmaxf(__fsub_rn(bxl, sx), __fsub_rn(sx, bxh)), 0.f);
        float dyc = fmaxf(fmaxf(__fsub_rn(byl, sy), __fsub_rn(sy, byh)), 0.f);
        float dzc = fmaxf(fmaxf(__fsub_rn(bzl, sz), __fsub_rn(sz, bzh)), 0.f);
        float LB = dxc * dxc + dyc * dyc + dzc * dzc;
        float LBm = LB * 0.999f - 1e-6f;     // down-biased: skip is exact
        if (!__all_sync(0xFFFFFFFFu, LBm >= bv)) {
            unsigned long long nsx = pk2(-sx, -sx);
            unsigned long long nsy = pk2(-sy, -sy);
            unsigned long long nsz = pk2(-sz, -sz);
            float nbv = 0.f;
#pragma unroll
            for (int p = 0; p < NPAIR; p++) {
                float2 xp = xs2[pbase + p * 32];
                float2 yp = ys2[pbase + p * 32];
                float2 zp = zs2[pbase + p * 32];
                unsigned long long dx2 = add2(pk2(xp.x, xp.y), nsx);
                unsigned long long dy2 = add2(pk2(yp.x, yp.y), nsy);
                unsigned long long dz2 = add2(pk2(zp.x, zp.y), nsz);
                unsigned long long d2 = add2(add2(mul2(dx2, dx2), mul2(dy2, dy2)),
                                             mul2(dz2, dz2));
                float d0, d1;
                upk2(d2, d0, d1);
                mindL[p] = fminf(mindL[p], d0);
                mindH[p] = fminf(mindH[p], d1);
                nbv = fmaxf(nbv, fmaxf(mindL[p], mindH[p]));
            }
            uint32_t nbi = 0xFFFFFFFFu;
#pragma unroll
            for (int p = 0; p < NPAIR; p++) {
                nbi = (mindL[p] == nbv) ? min(nbi, pkL[p]) : nbi;
                nbi = (mindH[p] == nbv) ? min(nbi, pkH[p]) : nbi;
            }
            bv = nbv;
            bi = nbi;
        }
    }
}

// ---------------------------------------------------------------------------
// ball query + fused centroid gather: one warp per query
// ---------------------------------------------------------------------------
__global__ void ballq_kernel(const float* __restrict__ xyz, const int* __restrict__ idxInt,
                             float* __restrict__ newxyz, float* __restrict__ outXyz,
                             int* __restrict__ ballIdx)
{
    __shared__ int lists[8][32];
    int warp = threadIdx.x >> 5, lane = threadIdx.x & 31;
    int q = blockIdx.x * 8 + warp;
    int b = q >> 10;
    const float* X = xyz + (size_t)b * NPTS * 3;
    int sel = idxInt[q];
    float qx = X[sel * 3], qy = X[sel * 3 + 1], qz = X[sel * 3 + 2];
    if (lane < 3) {
        float v = X[sel * 3 + lane];
        newxyz[q * 3 + lane] = v;
        outXyz[q * 3 + lane] = v;
    }
    const float R2 = (float)(0.3 * 0.3);
    int cnt = 0;
    for (int chunk = 0; chunk < NPTS / 32; chunk++) {
        int p = chunk * 32 + lane;
        float dx = __fsub_rn(qx, X[p * 3 + 0]);
        float dy = __fsub_rn(qy, X[p * 3 + 1]);
        float dz = __fsub_rn(qz, X[p * 3 + 2]);
        float d2 = __fadd_rn(__fadd_rn(__fmul_rn(dx, dx), __fmul_rn(dy, dy)),
                             __fmul_rn(dz, dz));
        bool in = (d2 <= R2);
        unsigned m = __ballot_sync(0xFFFFFFFFu, in);
        if (m) {
            int pos = cnt + __popc(m & ((1u << lane) - 1u));
            if (in && pos < 32) lists[warp][pos] = p;
            cnt += __popc(m);
            if (cnt >= 32) break;
        }
    }
    __syncwarp();
    int c = cnt < 32 ? cnt : 32;
    int v = (lane < c) ? lists[warp][lane] : lists[warp][0];
    ballIdx[q * 32 + lane] = v;
}

// ---------------------------------------------------------------------------
// final maxpool (BN3 finalize fused)
// ---------------------------------------------------------------------------
__global__ void maxpool_final(const float* __restrict__ pmax, const float* __restrict__ pmin,
                              const float* __restrict__ g3, const float* __restrict__ b3,
                              float* __restrict__ outFeat)
{
    __shared__ float sa_, sc_;
    int t = blockIdx.x * blockDim.x + threadIdx.x;   // 1048576
    int m = t >> 12;
    if (threadIdx.x == 0) bn_affine(3, m, (double)NCOLS2D, g3, b3, sa_, sc_);
    __syncthreads();
    float a = sa_, c = sc_;
    int cent = t & 4095;
    float y = (a >= 0.f) ? pmax[t] : pmin[t];
    float v = fmaxf(fmaf(a, y, c), 0.f);
    int b = cent >> 10, s = cent & 1023;
    outFeat[(((size_t)b * 256 + m) << 10) + s] = v;
}

// ---------------------------------------------------------------------------
extern "C" void kernel_launch(void* const* d_in, const int* in_sizes, int n_in,
                              void* d_out, int out_size)
{
    const float* xyz      = (const float*)d_in[0];
    const float* features = (const float*)d_in[1];
    const float* w1  = (const float*)d_in[2];
    const float* g1  = (const float*)d_in[3];
    const float* b1  = (const float*)d_in[4];
    const float* w2  = (const float*)d_in[5];
    const float* g2  = (const float*)d_in[6];
    const float* b2  = (const float*)d_in[7];
    const float* w3  = (const float*)d_in[8];
    const float* g3  = (const float*)d_in[9];
    const float* b3  = (const float*)d_in[10];
    const float* fw1 = (const float*)d_in[11];
    const float* fg1 = (const float*)d_in[12];
    const float* fb1 = (const float*)d_in[13];
    const float* fw2 = (const float*)d_in[14];
    const float* fbias2 = (const float*)d_in[15];

    float* out = (float*)d_out;
    float* outXyz    = out + OFS_XYZ;
    float* outFeat   = out + OFS_FEAT;
    float* outIdx    = out + OFS_IDX;
    float* outScores = out + OFS_SCORES;

    float* scr = nullptr;
    cudaGetSymbolAddress((void**)&scr, g_scratch);
    float* y1d    = scr + O_Y1D;
    float* y1T    = scr + O_Y1T;
    float* y2T    = scr + O_Y2T;
    float* p3max  = scr + O_P3MAX;
    float* p3min  = scr + O_P3MIN;
    float* margin = scr + O_MARGIN;
    float* newxyz = scr + O_NEWXYZ;
    float* wpad   = scr + O_WPAD;
    float* featT  = scr + O_FEATT;
    int* fgmask   = (int*)(scr + O_FGMASK);
    int* idxInt   = (int*)(scr + O_INDICES);
    int* ballIdx  = (int*)(scr + O_BALL);
    int* fpsPid   = (int*)(scr + O_FPSPID);

    gemm_fused<4><<<dim3(NCOLS1D / 128, 1), 256>>>(fw1, features, y1d, 128, NCOLS1D, 0);
    maskhead_kernel<<<NCOLS1D / 256, 256>>>(y1d, fg1, fb1, fw2, fbias2, outScores, margin);
    select_kernel<<<4, 256>>>(margin, fgmask);

    cudaFuncSetAttribute(fps_kernel, cudaFuncAttributeMaxDynamicSharedMemorySize, 14336 * 12);
    fps_kernel<<<8, 1024, 14336 * 12>>>(xyz, fgmask, fpsPid, idxInt, outIdx);

    prep_kernel<<<80, 256>>>(w1, wpad);
    transpose_kernel<<<dim3(NPTS / 32, CIN / 32, BATCH), dim3(32, 8)>>>(features, featT);
    ballq_kernel<<<NPOINT * BATCH / 8, 256>>>(xyz, idxInt, newxyz, outXyz, ballIdx);

    // conv1: NT=128, B gathered on the fly; K permuted [feat|xyz|pad]
    {
        auto k = conv_mma<KX1, 128, -1, 1, 0, 1>;
        size_t sm = (size_t)(128 + 128) * (KX1 + 4) * 4;
        cudaFuncSetAttribute(k, cudaFuncAttributeMaxDynamicSharedMemorySize, (int)sm);
        k<<<dim3(NCOLS2D / 128, 1), 256, sm>>>(wpad, featT, y1T, nullptr, nullptr,
                                               nullptr, nullptr, ballIdx, xyz, newxyz);
    }
    // conv2: NT=64 (occ 2), BN1+relu on B-load
    {
        auto k = conv_mma<128, 64, 1, 2, 0, 0>;
        size_t sm = (size_t)(128 + 64) * 132 * 4;
        cudaFuncSetAttribute(k, cudaFuncAttributeMaxDynamicSharedMemorySize, (int)sm);
        k<<<dim3(NCOLS2D / 64, 1), 256, sm>>>(w2, y1T, y2T, nullptr, nullptr, g1, b1,
                                              nullptr, nullptr, nullptr);
    }
    // conv3: NT=64 (occ 2), M=256 via grid.y=2, BN2+relu on B-load, pool fused
    {
        auto k = conv_mma<128, 64, 2, 3, 1, 0>;
        size_t sm = (size_t)(128 + 64) * 132 * 4;
        cudaFuncSetAttribute(k, cudaFuncAttributeMaxDynamicSharedMemorySize, (int)sm);
        k<<<dim3(NCOLS2D / 64, 2), 256, sm>>>(w3, y2T, nullptr, p3max, p3min, g2, b2,
                                              nullptr, nullptr, nullptr);
    }
    maxpool_final<<<(256 * 4096) / 256, 256>>>(p3max, p3min, g3, b3, outFeat);
}

// round 16
// speedup vs baseline: 1.0160x; 1.0078x over previous
#include <cuda_runtime.h>
#include <cuda_bf16.h>
#include <cstdint>

#define BATCH   4
#define NPTS    16384
#define CIN     128
#define NPOINT  1024
#define FG_NS   512
#define TOPK_K  2048
#define NCOLS2D 131072
#define NCOLS1D 65536
#define KX1     160

#define OFS_XYZ    0
#define OFS_FEAT   12288
#define OFS_IDX    (12288 + 1048576)
#define OFS_SCORES (12288 + 1048576 + 4096)

#define O_Y1D     0ull
#define O_Y1T     25165824ull
#define O_Y2T     41943040ull
#define O_P3MAX   58720256ull
#define O_P3MIN   59768832ull
#define O_MARGIN  60817408ull
#define O_NEWXYZ  60882944ull
#define O_FGMASK  60895232ull
#define O_INDICES 60960768ull
#define O_BALL    60964864ull
#define O_WPAD    61095936ull
#define O_FEATT   61116416ull
#define O_FPSPID  69505024ull
#define SCRATCH_FLOATS 69619712ull

__device__ float g_scratch[SCRATCH_FLOATS];
__device__ double g_sum[4][256];
__device__ double g_sumsq[4][256];

// ---------------------------------------------------------------------------
__device__ __forceinline__ float tf32r(float x) {
    uint32_t u;
    asm("cvt.rna.tf32.f32 %0, %1;" : "=r"(u) : "f"(x));
    return __uint_as_float(u);
}
__device__ __forceinline__ void mma_tf32(float* c, uint32_t a0, uint32_t a1,
                                         uint32_t a2, uint32_t a3,
                                         uint32_t b0, uint32_t b1) {
    asm("mma.sync.aligned.m16n8k8.row.col.f32.tf32.tf32.f32 "
        "{%0,%1,%2,%3},{%4,%5,%6,%7},{%8,%9},{%0,%1,%2,%3};"
        : "+f"(c[0]), "+f"(c[1]), "+f"(c[2]), "+f"(c[3])
        : "r"(a0), "r"(a1), "r"(a2), "r"(a3), "r"(b0), "r"(b1));
}
__device__ __forceinline__ void bn_affine(int layer, int m, double cnt,
                                          const float* g, const float* beta,
                                          float& a, float& c) {
    double mu = g_sum[layer][m] / cnt;
    double var = g_sumsq[layer][m] / cnt - mu * mu;
    a = g[m] * rsqrtf((float)var + 1e-5f);
    c = beta[m] - (float)mu * a;
}
// packed f32x2 helpers (per-element .rn == scalar rn)
__device__ __forceinline__ unsigned long long pk2(float lo, float hi) {
    unsigned long long r;
    asm("mov.b64 %0, {%1, %2};" : "=l"(r) : "f"(lo), "f"(hi));
    return r;
}
__device__ __forceinline__ unsigned long long add2(unsigned long long a,
                                                   unsigned long long b) {
    unsigned long long d;
    asm("add.rn.f32x2 %0, %1, %2;" : "=l"(d) : "l"(a), "l"(b));
    return d;
}
__device__ __forceinline__ unsigned long long mul2(unsigned long long a,
                                                   unsigned long long b) {
    unsigned long long d;
    asm("mul.rn.f32x2 %0, %1, %2;" : "=l"(d) : "l"(a), "l"(b));
    return d;
}
__device__ __forceinline__ unsigned long long fma2(unsigned long long a,
                                                   unsigned long long b,
                                                   unsigned long long c) {
    unsigned long long d;
    asm("fma.rn.f32x2 %0, %1, %2, %3;" : "=l"(d) : "l"(a), "l"(b), "l"(c));
    return d;
}
__device__ __forceinline__ void upk2(unsigned long long v, float& lo, float& hi) {
    asm("mov.b64 {%0, %1}, %2;" : "=f"(lo), "=f"(hi) : "l"(v));
}

// ---------------------------------------------------------------------------
// setup: (CTA<80) zero stats + permuted padded w1; (CTA>=80) features transpose
// block = (32,8) for both halves
// ---------------------------------------------------------------------------
__global__ void setup_kernel(const float* __restrict__ w1, float* __restrict__ wpad,
                             const float* __restrict__ features, float* __restrict__ featT)
{
    int tid = threadIdx.y * 32 + threadIdx.x;
    if (blockIdx.x < 80) {
        int t = blockIdx.x * 256 + tid;   // 20480 = 128*160
        if (blockIdx.x == 0) {
            double* s  = &g_sum[0][0];
            double* s2 = &g_sumsq[0][0];
            for (int i = tid; i < 4 * 256; i += 256) { s[i] = 0.0; s2[i] = 0.0; }
        }
        int o = t / KX1, c = t % KX1;
        float v = 0.f;
        if (c < 128)       v = w1[o * 131 + c + 3];
        else if (c < 131)  v = w1[o * 131 + c - 128];
        wpad[t] = v;
        return;
    }
    __shared__ float tile[32][33];
    int bid = blockIdx.x - 80;            // 8192 = 512 * 4 * 4
    int nx = bid & 511;
    int cy = (bid >> 9) & 3;
    int b  = bid >> 11;
    int n0 = nx * 32, c0 = cy * 32;
    int x = threadIdx.x, y = threadIdx.y;
#pragma unroll
    for (int k = 0; k < 32; k += 8)
        tile[y + k][x] = features[((size_t)b * CIN + c0 + y + k) * NPTS + n0 + x];
    __syncthreads();
#pragma unroll
    for (int k = 0; k < 32; k += 8)
        featT[((size_t)b * NPTS + n0 + y + k) * CIN + c0 + x] = tile[x][y + k];
}

// ---------------------------------------------------------------------------
// tf32 mma.sync conv GEMM. Tile = 128 rows x NT cols.
// ---------------------------------------------------------------------------
template<int KE, int NT, int AFF, int STATS, int POOL, int GB>
__global__ void __launch_bounds__(256, (NT == 64) ? 2 : 1) conv_mma(
    const float* __restrict__ W, const float* __restrict__ Xin,
    float* __restrict__ Yout, float* __restrict__ poolMax, float* __restrict__ poolMin,
    const float* __restrict__ gPrev, const float* __restrict__ bPrev,
    const int* __restrict__ ballIdx, const float* __restrict__ xyzIn,
    const float* __restrict__ newxyz)
{
    constexpr int LDK = KE + 4;
    constexpr int NWN = (NT == 128) ? 4 : 2;
    constexpr int MA  = (NT == 128) ? 4 : 2;
    extern __shared__ float sm[];
    float* As = sm;                     // [128][LDK]
    float* Bs = sm + 128 * LDK;         // [NT][LDK]
    __shared__ __align__(16) float affA[128];
    __shared__ __align__(16) float affC[128];
    const int tid = threadIdx.x;
    const int wid = tid >> 5, lane = tid & 31;
    const int g = lane >> 2, t = lane & 3;
    const int wm = wid / NWN, wn = wid % NWN;
    const int rowBase = blockIdx.y * 128;
    const int colBase = blockIdx.x * NT;

    if (AFF >= 0) {
        if (tid < 128)
            bn_affine(AFF, tid, (double)NCOLS2D, gPrev, bPrev, affA[tid], affC[tid]);
        __syncthreads();
    }
    for (int i = tid; i < 128 * (KE / 4); i += 256) {
        int r = i / (KE / 4), k = (i % (KE / 4)) * 4;
        float4 v = *(const float4*)(W + (size_t)(rowBase + r) * KE + k);
        As[r * LDK + k + 0] = tf32r(v.x);
        As[r * LDK + k + 1] = tf32r(v.y);
        As[r * LDK + k + 2] = tf32r(v.z);
        As[r * LDK + k + 3] = tf32r(v.w);
    }
    for (int i = tid; i < NT * (KE / 4); i += 256) {
        int r = i / (KE / 4), k = (i % (KE / 4)) * 4;
        float4 v;
        if (GB) {
            int col = colBase + r;
            int idx = ballIdx[col];
            int bb = col >> 15;
            if (k < 128) {
                v = *(const float4*)(Xin + ((size_t)(bb * NPTS + idx)) * 128 + k);
            } else if (k == 128) {
                int q = col >> 5;
                const float* xp = xyzIn + ((size_t)bb * NPTS + idx) * 3;
                v.x = __fsub_rn(xp[0], newxyz[q * 3 + 0]);
                v.y = __fsub_rn(xp[1], newxyz[q * 3 + 1]);
                v.z = __fsub_rn(xp[2], newxyz[q * 3 + 2]);
                v.w = 0.f;
            } else {
                v = make_float4(0.f, 0.f, 0.f, 0.f);
            }
        } else {
            v = *(const float4*)(Xin + (size_t)(colBase + r) * KE + k);
            if (AFF >= 0) {
                float4 av = *(const float4*)&affA[k];
                float4 cv = *(const float4*)&affC[k];
                v.x = fmaxf(fmaf(av.x, v.x, cv.x), 0.f);
                v.y = fmaxf(fmaf(av.y, v.y, cv.y), 0.f);
                v.z = fmaxf(fmaf(av.z, v.z, cv.z), 0.f);
                v.w = fmaxf(fmaf(av.w, v.w, cv.w), 0.f);
            }
        }
        Bs[r * LDK + k + 0] = tf32r(v.x);
        Bs[r * LDK + k + 1] = tf32r(v.y);
        Bs[r * LDK + k + 2] = tf32r(v.z);
        Bs[r * LDK + k + 3] = tf32r(v.w);
    }
    __syncthreads();

    float acc[MA][4][4];
#pragma unroll
    for (int i = 0; i < MA; i++)
#pragma unroll
        for (int j = 0; j < 4; j++)
#pragma unroll
            for (int c = 0; c < 4; c++) acc[i][j][c] = 0.f;

    const float* Arow0 = As + (size_t)(wm * (MA * 16) + g) * LDK + t;
    const float* Arow8 = Arow0 + 8 * LDK;
    const float* Bcol0 = Bs + (size_t)(wn * 32 + g) * LDK + t;

#pragma unroll 4
    for (int ks = 0; ks < KE / 8; ks++) {
        const int k0 = ks * 8;
        uint32_t a[MA][4], b[4][2];
#pragma unroll
        for (int ma = 0; ma < MA; ma++) {
            const float* p0 = Arow0 + ma * 16 * LDK + k0;
            const float* p8 = Arow8 + ma * 16 * LDK + k0;
            a[ma][0] = __float_as_uint(p0[0]);
            a[ma][1] = __float_as_uint(p8[0]);
            a[ma][2] = __float_as_uint(p0[4]);
            a[ma][3] = __float_as_uint(p8[4]);
        }
#pragma unroll
        for (int nb = 0; nb < 4; nb++) {
            const float* pb = Bcol0 + nb * 8 * LDK + k0;
            b[nb][0] = __float_as_uint(pb[0]);
            b[nb][1] = __float_as_uint(pb[4]);
        }
#pragma unroll
        for (int ma = 0; ma < MA; ma++)
#pragma unroll
            for (int nb = 0; nb < 4; nb++)
                mma_tf32(acc[ma][nb], a[ma][0], a[ma][1], a[ma][2], a[ma][3],
                         b[nb][0], b[nb][1]);
    }

#pragma unroll
    for (int ma = 0; ma < MA; ma++) {
        int r0 = wm * (MA * 16) + ma * 16 + g;
        float s0 = 0.f, q0 = 0.f, s1 = 0.f, q1 = 0.f;
        float mx0 = -1e30f, mn0 = 1e30f, mx1 = -1e30f, mn1 = 1e30f;
#pragma unroll
        for (int nb = 0; nb < 4; nb++) {
            float c0 = acc[ma][nb][0], c1 = acc[ma][nb][1];
            float c2 = acc[ma][nb][2], c3 = acc[ma][nb][3];
            s0 += c0 + c1; q0 = fmaf(c0, c0, fmaf(c1, c1, q0));
            s1 += c2 + c3; q1 = fmaf(c2, c2, fmaf(c3, c3, q1));
            if (POOL) {
                mx0 = fmaxf(mx0, fmaxf(c0, c1)); mn0 = fminf(mn0, fminf(c0, c1));
                mx1 = fmaxf(mx1, fmaxf(c2, c3)); mn1 = fminf(mn1, fminf(c2, c3));
            }
        }
#pragma unroll
        for (int off = 1; off < 4; off <<= 1) {
            s0 += __shfl_xor_sync(0xFFFFFFFFu, s0, off);
            q0 += __shfl_xor_sync(0xFFFFFFFFu, q0, off);
            s1 += __shfl_xor_sync(0xFFFFFFFFu, s1, off);
            q1 += __shfl_xor_sync(0xFFFFFFFFu, q1, off);
            if (POOL) {
                mx0 = fmaxf(mx0, __shfl_xor_sync(0xFFFFFFFFu, mx0, off));
                mn0 = fminf(mn0, __shfl_xor_sync(0xFFFFFFFFu, mn0, off));
                mx1 = fmaxf(mx1, __shfl_xor_sync(0xFFFFFFFFu, mx1, off));
                mn1 = fminf(mn1, __shfl_xor_sync(0xFFFFFFFFu, mn1, off));
            }
        }
        if (t == 0) {
            atomicAdd(&g_sum[STATS][rowBase + r0], (double)s0);
            atomicAdd(&g_sumsq[STATS][rowBase + r0], (double)q0);
            atomicAdd(&g_sum[STATS][rowBase + r0 + 8], (double)s1);
            atomicAdd(&g_sumsq[STATS][rowBase + r0 + 8], (double)q1);
            if (POOL) {
                int cent = (colBase >> 5) + wn;
                poolMax[(size_t)(rowBase + r0) * 4096 + cent] = mx0;
                poolMin[(size_t)(rowBase + r0) * 4096 + cent] = mn0;
                poolMax[(size_t)(rowBase + r0 + 8) * 4096 + cent] = mx1;
                poolMin[(size_t)(rowBase + r0 + 8) * 4096 + cent] = mn1;
            }
        }
    }

    if (!POOL) {
        __syncthreads();
        float* Ct = As;   // [NT cols][132]
#pragma unroll
        for (int ma = 0; ma < MA; ma++) {
            int r0 = wm * (MA * 16) + ma * 16 + g;
#pragma unroll
            for (int nb = 0; nb < 4; nb++) {
                int col0 = wn * 32 + nb * 8 + 2 * t;
                Ct[col0 * 132 + r0]           = acc[ma][nb][0];
                Ct[(col0 + 1) * 132 + r0]     = acc[ma][nb][1];
                Ct[col0 * 132 + r0 + 8]       = acc[ma][nb][2];
                Ct[(col0 + 1) * 132 + r0 + 8] = acc[ma][nb][3];
            }
        }
        __syncthreads();
        for (int i = tid; i < NT * 32; i += 256) {
            int col = i >> 5;
            int r4 = (i & 31) * 4;
            float4 v = *(float4*)&Ct[col * 132 + r4];
            *(float4*)(Yout + (size_t)(colBase + col) * 128 + r4) = v;
        }
    }
}

// ---------------------------------------------------------------------------
// SIMT SGEMM for mask-head conv — fp32 exact via packed fma.rn.f32x2, occ 3
// ---------------------------------------------------------------------------
template<int RT>
__global__ void __launch_bounds__(256, 3) gemm_fused(
    const float* __restrict__ A, const float* __restrict__ B, float* __restrict__ C,
    int K, int Ncols, int statsLayer)
{
    constexpr int TM = RT * 16;
    __shared__ float As[2][16][TM + 4];
    __shared__ __align__(16) float Bs[2][16][128];
    const int tid = threadIdx.x;
    const int tx = tid & 15, ty = tid >> 4;
    const int rowBase = blockIdx.y * TM;
    const int colBase = blockIdx.x * 128;

    unsigned long long acc2[RT][4];
#pragma unroll
    for (int i = 0; i < RT; i++)
#pragma unroll
        for (int j = 0; j < 4; j++) acc2[i][j] = 0ull;

    const int ktiles = K >> 4;
    {
#pragma unroll
        for (int l = 0; l < RT; l++) {
            int i = l * 256 + tid;
            int r = i >> 4, kk = i & 15;
            As[0][kk][r] = A[(rowBase + r) * K + kk];
        }
#pragma unroll
        for (int l = 0; l < 2; l++) {
            int i = l * 256 + tid;
            int kk = i >> 5, c4 = i & 31;
            int gc = colBase + c4 * 4;
            const float* src = B + (((size_t)(gc >> 14) * 128 + kk) << 14) + (gc & 16383);
            *(float4*)&Bs[0][kk][c4 * 4] = *(const float4*)src;
        }
    }
    __syncthreads();

    float pa[RT];
    float4 pb0, pb1;
    for (int kt = 0; kt < ktiles; kt++) {
        const int cur = kt & 1, nxt = cur ^ 1;
        const bool more = (kt + 1 < ktiles);
        if (more) {
            const int k0 = (kt + 1) << 4;
#pragma unroll
            for (int l = 0; l < RT; l++) {
                int i = l * 256 + tid;
                int r = i >> 4, kk = i & 15;
                pa[l] = A[(rowBase + r) * K + k0 + kk];
            }
#pragma unroll
            for (int l = 0; l < 2; l++) {
                int i = l * 256 + tid;
                int kk = i >> 5, c4 = i & 31;
                int gk = k0 + kk, gc = colBase + c4 * 4;
                const float* src = B + (((size_t)(gc >> 14) * 128 + gk) << 14) + (gc & 16383);
                float4 v = *(const float4*)src;
                if (l == 0) pb0 = v; else pb1 = v;
            }
        }
#pragma unroll
        for (int kk = 0; kk < 16; kk++) {
            const unsigned long long* rbp =
                (const unsigned long long*)&Bs[cur][kk][tx * 8];
            unsigned long long rb2[4];
#pragma unroll
            for (int j = 0; j < 4; j++) rb2[j] = rbp[j];
#pragma unroll
            for (int i = 0; i < RT; i++) {
                float av = As[cur][kk][ty * RT + i];
                unsigned long long ra2 = pk2(av, av);
#pragma unroll
                for (int j = 0; j < 4; j++)
                    acc2[i][j] = fma2(ra2, rb2[j], acc2[i][j]);
            }
        }
        if (more) {
#pragma unroll
            for (int l = 0; l < RT; l++) {
                int i = l * 256 + tid;
                int r = i >> 4, kk = i & 15;
                As[nxt][kk][r] = pa[l];
            }
            { int kk = tid >> 5, c4 = tid & 31; *(float4*)&Bs[nxt][kk][c4 * 4] = pb0; }
            { int i = 256 + tid; int kk = i >> 5, c4 = i & 31; *(float4*)&Bs[nxt][kk][c4 * 4] = pb1; }
        }
        __syncthreads();
    }
    float acc[RT][8];
#pragma unroll
    for (int i = 0; i < RT; i++)
#pragma unroll
        for (int j = 0; j < 4; j++)
            upk2(acc2[i][j], acc[i][2 * j], acc[i][2 * j + 1]);
#pragma unroll
    for (int i = 0; i < RT; i++) {
        float* dst = C + (size_t)(rowBase + ty * RT + i) * Ncols + colBase + tx * 8;
        *(float4*)dst       = make_float4(acc[i][0], acc[i][1], acc[i][2], acc[i][3]);
        *(float4*)(dst + 4) = make_float4(acc[i][4], acc[i][5], acc[i][6], acc[i][7]);
    }
#pragma unroll
    for (int i = 0; i < RT; i++) {
        float s = 0.f, s2 = 0.f;
#pragma unroll
        for (int j = 0; j < 8; j++) { float v = acc[i][j]; s += v; s2 = fmaf(v, v, s2); }
#pragma unroll
        for (int off = 1; off < 16; off <<= 1) {
            s  += __shfl_xor_sync(0xFFFFFFFFu, s, off);
            s2 += __shfl_xor_sync(0xFFFFFFFFu, s2, off);
        }
        if (tx == 0) {
            int gr = rowBase + ty * RT + i;
            atomicAdd(&g_sum[statsLayer][gr], (double)s);
            atomicAdd(&g_sumsq[statsLayer][gr], (double)s2);
        }
    }
}

// ---------------------------------------------------------------------------
// mask head (BN0 finalize fused)
// ---------------------------------------------------------------------------
__global__ void maskhead_kernel(const float* __restrict__ y1d,
                                const float* __restrict__ fg1,
                                const float* __restrict__ fb1,
                                const float* __restrict__ fw2,
                                const float* __restrict__ fbias2,
                                float* __restrict__ outScores,
                                float* __restrict__ margin)
{
    __shared__ float affA[64], affC[64];
    if (threadIdx.x < 64)
        bn_affine(0, threadIdx.x, (double)NCOLS1D, fg1, fb1,
                  affA[threadIdx.x], affC[threadIdx.x]);
    __syncthreads();
    int col = blockIdx.x * blockDim.x + threadIdx.x;
    int b = col >> 14, n = col & 16383;
    float s0 = fbias2[0], s1 = fbias2[1];
#pragma unroll 4
    for (int c = 0; c < 64; c++) {
        float v = fmaxf(fmaf(affA[c], y1d[(size_t)c * NCOLS1D + col], affC[c]), 0.f);
        s0 = fmaf(fw2[c], v, s0);
        s1 = fmaf(fw2[64 + c], v, s1);
    }
    outScores[b * 32768 + n]         = s0;
    outScores[b * 32768 + 16384 + n] = s1;
    float mx = fmaxf(s0, s1);
    float e0 = expf(s0 - mx), e1 = expf(s1 - mx);
    margin[col] = (e1 - e0) / (e0 + e1);
}

// ---------------------------------------------------------------------------
// exact top-2048 per batch (radix select on 64-bit key), 1024 threads
// ---------------------------------------------------------------------------
__device__ __forceinline__ unsigned long long makeKey(float f, int i)
{
    unsigned u = __float_as_uint(f);
    u = (u & 0x80000000u) ? ~u : (u | 0x80000000u);
    return ((unsigned long long)u << 32) | (unsigned)(0xFFFFFFFFu - (unsigned)i);
}

__global__ void select_kernel(const float* __restrict__ margin, int* __restrict__ fgmask)
{
    __shared__ unsigned hist[256];
    __shared__ unsigned long long sprefix;
    __shared__ int skrem;
    int b = blockIdx.x, tid = threadIdx.x;
    const float* M = margin + b * NPTS;
    if (tid == 0) { sprefix = 0ull; skrem = TOPK_K; }
    __syncthreads();
    for (int pos = 56; pos >= 0; pos -= 8) {
        if (tid < 256) hist[tid] = 0;
        __syncthreads();
        unsigned long long pref = sprefix;
        for (int i = tid; i < NPTS; i += 1024) {
            unsigned long long key = makeKey(M[i], i);
            bool act = (pos == 56) || ((key >> (pos + 8)) == (pref >> (pos + 8)));
            if (act) atomicAdd(&hist[(unsigned)(key >> pos) & 255u], 1u);
        }
        __syncthreads();
        if (tid == 0) {
            int k = skrem;
            int v = 255;
            while (v > 0 && (int)hist[v] < k) { k -= (int)hist[v]; v--; }
            skrem = k;
            sprefix = pref | ((unsigned long long)(unsigned)v << pos);
        }
        __syncthreads();
    }
    unsigned long long kth = sprefix;
    for (int i = tid; i < NPTS; i += 1024)
        fgmask[b * NPTS + i] = (makeKey(M[i], i) >= kth) ? 1 : 0;
}

// ---------------------------------------------------------------------------
// masked FPS v4 (R13): Morton sort (512 cells), warp boxes, f32x2 packed math,
// ONE barrier/iter via parity double-buffered candidates. Exact.
// ---------------------------------------------------------------------------
#define WSLOT 448
#define NPAIR 7

__device__ __forceinline__ int spread3(int v) {
    return (v & 1) | ((v & 2) << 2) | ((v & 4) << 4);
}
__device__ __forceinline__ int cellOf(float x, float y, float z) {
    int cx = min(7, max(0, (int)(x * 8.f)));
    int cy = min(7, max(0, (int)(y * 8.f)));
    int cz = min(7, max(0, (int)(z * 8.f)));
    return spread3(cx) | (spread3(cy) << 1) | (spread3(cz) << 2);
}

__global__ void __launch_bounds__(1024, 1) fps_kernel(
    const float* __restrict__ xyz, const int* __restrict__ fgmask,
    int* __restrict__ fpsPid, int* __restrict__ idxInt, float* __restrict__ idxOutF)
{
    extern __shared__ float sh[];
    float* xs = sh;               // 14336
    float* ys = sh + 14336;
    float* zs = sh + 28672;
    __shared__ int hist[512];
    __shared__ uint2 warpRes[2][32];

    const int blk = blockIdx.x, b = blk >> 1, isFg = !(blk & 1);
    const float* X = xyz + (size_t)b * NPTS * 3;
    const int* Mk = fgmask + b * NPTS;
    int* pidbuf = fpsPid + blk * 14336;
    const int tid = threadIdx.x, lane = tid & 31, wid = tid >> 5;
    const int cnt = isFg ? TOPK_K : (NPTS - TOPK_K);   // 2048 / 14336
    const int nwActive = isFg ? 5 : 32;
    const int padded = nwActive * WSLOT;               // 2240 / 14336
    const int nbar = nwActive * 32;

    if (tid < 512) hist[tid] = 0;
    __syncthreads();
    for (int i = tid; i < NPTS; i += 1024) {
        int m = Mk[i]; if (!isFg) m = !m;
        if (m) atomicAdd(&hist[cellOf(X[i*3], X[i*3+1], X[i*3+2])], 1);
    }
    __syncthreads();
    {
        int* sa = (int*)xs;
        int* sb = sa + 512;
        if (tid < 512) sa[tid] = hist[tid];
        __syncthreads();
        for (int off = 1; off < 512; off <<= 1) {
            int v = 0;
            if (tid < 512) v = sa[tid] + (tid >= off ? sa[tid - off] : 0);
            __syncthreads();
            if (tid < 512) sb[tid] = v;
            int* tp = sa; sa = sb; sb = tp;
            __syncthreads();
        }
        int excl = 0;
        if (tid < 512) excl = sa[tid] - hist[tid];
        __syncthreads();
        if (tid < 512) hist[tid] = excl;
    }
    __syncthreads();
    for (int i = tid; i < NPTS; i += 1024) {
        int m = Mk[i]; if (!isFg) m = !m;
        if (m) {
            float x = X[i*3], y = X[i*3+1], z = X[i*3+2];
            int pos = atomicAdd(&hist[cellOf(x, y, z)], 1);
            xs[pos] = x; ys[pos] = y; zs[pos] = z;
            pidbuf[pos] = i;
        }
    }
    __syncthreads();
    for (int i = cnt + tid; i < padded; i += 1024) {
        xs[i] = xs[cnt-1]; ys[i] = ys[cnt-1]; zs[i] = zs[cnt-1];
        pidbuf[i] = pidbuf[cnt-1];
    }
    __syncthreads();

    if (wid >= nwActive) {
        if (lane == 0) {
            warpRes[0][wid] = make_uint2(0u, 0xFFFFFFFFu);
            warpRes[1][wid] = make_uint2(0u, 0xFFFFFFFFu);
        }
        return;
    }

    const int wbase = wid * WSLOT;
    const float2* xs2 = (const float2*)xs;
    const float2* ys2 = (const float2*)ys;
    const float2* zs2 = (const float2*)zs;
    const int pbase = (wbase >> 1) + lane;

    float mindL[NPAIR], mindH[NPAIR];
    uint32_t pkL[NPAIR], pkH[NPAIR];
    float bxl = 1e9f, bxh = -1e9f, byl = 1e9f, byh = -1e9f, bzl = 1e9f, bzh = -1e9f;
#pragma unroll
    for (int p = 0; p < NPAIR; p++) {
        int s0 = wbase + (p * 32 + lane) * 2;
        int2 pp = *(const int2*)&pidbuf[s0];
        pkL[p] = ((uint32_t)pp.x << 14) | (uint32_t)s0;
        pkH[p] = ((uint32_t)pp.y << 14) | (uint32_t)(s0 + 1);
        mindL[p] = 1e10f; mindH[p] = 1e10f;
        float2 xp = xs2[pbase + p * 32];
        float2 yp = ys2[pbase + p * 32];
        float2 zp = zs2[pbase + p * 32];
        bxl = fminf(bxl, fminf(xp.x, xp.y)); bxh = fmaxf(bxh, fmaxf(xp.x, xp.y));
        byl = fminf(byl, fminf(yp.x, yp.y)); byh = fmaxf(byh, fmaxf(yp.x, yp.y));
        bzl = fminf(bzl, fminf(zp.x, zp.y)); bzh = fmaxf(bzh, fmaxf(zp.x, zp.y));
    }
#pragma unroll
    for (int off = 16; off; off >>= 1) {
        bxl = fminf(bxl, __shfl_xor_sync(0xFFFFFFFFu, bxl, off));
        bxh = fmaxf(bxh, __shfl_xor_sync(0xFFFFFFFFu, bxh, off));
        byl = fminf(byl, __shfl_xor_sync(0xFFFFFFFFu, byl, off));
        byh = fmaxf(byh, __shfl_xor_sync(0xFFFFFFFFu, byh, off));
        bzl = fminf(bzl, __shfl_xor_sync(0xFFFFFFFFu, bzl, off));
        bzh = fmaxf(bzh, __shfl_xor_sync(0xFFFFFFFFu, bzh, off));
    }
    float bv = 1e10f;
    uint32_t bi = 0xFFFFFFFFu;
#pragma unroll
    for (int p = 0; p < NPAIR; p++) bi = min(bi, min(pkL[p], pkH[p]));

    const int outBase = b * NPOINT + (isFg ? 0 : FG_NS);
    for (int it = 0; it < FG_NS; it++) {
        const int s = it & 1;
        uint32_t key = __float_as_uint(bv);
        uint32_t kmax = __reduce_max_sync(0xFFFFFFFFu, key);
        uint32_t cmin = __reduce_min_sync(0xFFFFFFFFu, (key == kmax) ? bi : 0xFFFFFFFFu);
        if (lane == 0) warpRes[s][wid] = make_uint2(kmax, cmin);
        asm volatile("bar.sync 1, %0;" :: "r"(nbar) : "memory");
        uint2 e = warpRes[s][lane];
        uint32_t k2 = __reduce_max_sync(0xFFFFFFFFu, e.x);
        uint32_t c2 = __reduce_min_sync(0xFFFFFFFFu, (e.x == k2) ? e.y : 0xFFFFFFFFu);
        int slot = (int)(c2 & 0x3FFFu);
        if (wid == 0 && lane == 0) {
            int pid = (int)(c2 >> 14);
            idxInt[outBase + it] = pid;
            idxOutF[outBase + it] = (float)pid;
        }
        float sx = xs[slot], sy = ys[slot], sz = zs[slot];   // broadcast LDS
        float dxc = fmaxf(fmaxf(__fsub_rn(bxl, sx), __fsub_rn(sx, bxh)), 0.f);
        float dyc = fmaxf(fmaxf(__fsub_rn(byl, sy), __fsub_rn(sy, byh)), 0.f);
        float dzc = fmaxf(fmaxf(__fsub_rn(bzl, sz), __fsub_rn(sz, bzh)), 0.f);
        float LB = dxc * dxc + dyc * dyc + dzc * dzc;
        float LBm = LB * 0.999f - 1e-6f;     // down-biased: skip is exact
        if (!__all_sync(0xFFFFFFFFu, LBm >= bv)) {
            unsigned long long nsx = pk2(-sx, -sx);
            unsigned long long nsy = pk2(-sy, -sy);
            unsigned long long nsz = pk2(-sz, -sz);
            float nbv = 0.f;
#pragma unroll
            for (int p = 0; p < NPAIR; p++) {
                float2 xp = xs2[pbase + p * 32];
                float2 yp = ys2[pbase + p * 32];
                float2 zp = zs2[pbase + p * 32];
                unsigned long long dx2 = add2(pk2(xp.x, xp.y), nsx);
                unsigned long long dy2 = add2(pk2(yp.x, yp.y), nsy);
                unsigned long long dz2 = add2(pk2(zp.x, zp.y), nsz);
                unsigned long long d2 = add2(add2(mul2(dx2, dx2), mul2(dy2, dy2)),
                                             mul2(dz2, dz2));
                float d0, d1;
                upk2(d2, d0, d1);
                mindL[p] = fminf(mindL[p], d0);
                mindH[p] = fminf(mindH[p], d1);
                nbv = fmaxf(nbv, fmaxf(mindL[p], mindH[p]));
            }
            uint32_t nbi = 0xFFFFFFFFu;
#pragma unroll
            for (int p = 0; p < NPAIR; p++) {
                nbi = (mindL[p] == nbv) ? min(nbi, pkL[p]) : nbi;
                nbi = (mindH[p] == nbv) ? min(nbi, pkH[p]) : nbi;
            }
            bv = nbv;
            bi = nbi;
        }
    }
}

// ---------------------------------------------------------------------------
// ball query + fused centroid gather: one warp per query
// ---------------------------------------------------------------------------
__global__ void ballq_kernel(const float* __restrict__ xyz, const int* __restrict__ idxInt,
                             float* __restrict__ newxyz, float* __restrict__ outXyz,
                             int* __restrict__ ballIdx)
{
    __shared__ int lists[8][32];
    int warp = threadIdx.x >> 5, lane = threadIdx.x & 31;
    int q = blockIdx.x * 8 + warp;
    int b = q >> 10;
    const float* X = xyz + (size_t)b * NPTS * 3;
    int sel = idxInt[q];
    float qx = X[sel * 3], qy = X[sel * 3 + 1], qz = X[sel * 3 + 2];
    if (lane < 3) {
        float v = X[sel * 3 + lane];
        newxyz[q * 3 + lane] = v;
        outXyz[q * 3 + lane] = v;
    }
    const float R2 = (float)(0.3 * 0.3);
    int cnt = 0;
    for (int chunk = 0; chunk < NPTS / 32; chunk++) {
        int p = chunk * 32 + lane;
        float dx = __fsub_rn(qx, X[p * 3 + 0]);
        float dy = __fsub_rn(qy, X[p * 3 + 1]);
        float dz = __fsub_rn(qz, X[p * 3 + 2]);
        float d2 = __fadd_rn(__fadd_rn(__fmul_rn(dx, dx), __fmul_rn(dy, dy)),
                             __fmul_rn(dz, dz));
        bool in = (d2 <= R2);
        unsigned m = __ballot_sync(0xFFFFFFFFu, in);
        if (m) {
            int pos = cnt + __popc(m & ((1u << lane) - 1u));
            if (in && pos < 32) lists[warp][pos] = p;
            cnt += __popc(m);
            if (cnt >= 32) break;
        }
    }
    __syncwarp();
    int c = cnt < 32 ? cnt : 32;
    int v = (lane < c) ? lists[warp][lane] : lists[warp][0];
    ballIdx[q * 32 + lane] = v;
}

// ---------------------------------------------------------------------------
// final maxpool (BN3 finalize fused)
// ---------------------------------------------------------------------------
__global__ void maxpool_final(const float* __restrict__ pmax, const float* __restrict__ pmin,
                              const float* __restrict__ g3, const float* __restrict__ b3,
                              float* __restrict__ outFeat)
{
    __shared__ float sa_, sc_;
    int t = blockIdx.x * blockDim.x + threadIdx.x;   // 1048576
    int m = t >> 12;
    if (threadIdx.x == 0) bn_affine(3, m, (double)NCOLS2D, g3, b3, sa_, sc_);
    __syncthreads();
    float a = sa_, c = sc_;
    int cent = t & 4095;
    float y = (a >= 0.f) ? pmax[t] : pmin[t];
    float v = fmaxf(fmaf(a, y, c), 0.f);
    int b = cent >> 10, s = cent & 1023;
    outFeat[(((size_t)b * 256 + m) << 10) + s] = v;
}

// ---------------------------------------------------------------------------
extern "C" void kernel_launch(void* const* d_in, const int* in_sizes, int n_in,
                              void* d_out, int out_size)
{
    const float* xyz      = (const float*)d_in[0];
    const float* features = (const float*)d_in[1];
    const float* w1  = (const float*)d_in[2];
    const float* g1  = (const float*)d_in[3];
    const float* b1  = (const float*)d_in[4];
    const float* w2  = (const float*)d_in[5];
    const float* g2  = (const float*)d_in[6];
    const float* b2  = (const float*)d_in[7];
    const float* w3  = (const float*)d_in[8];
    const float* g3  = (const float*)d_in[9];
    const float* b3  = (const float*)d_in[10];
    const float* fw1 = (const float*)d_in[11];
    const float* fg1 = (const float*)d_in[12];
    const float* fb1 = (const float*)d_in[13];
    const float* fw2 = (const float*)d_in[14];
    const float* fbias2 = (const float*)d_in[15];

    float* out = (float*)d_out;
    float* outXyz    = out + OFS_XYZ;
    float* outFeat   = out + OFS_FEAT;
    float* outIdx    = out + OFS_IDX;
    float* outScores = out + OFS_SCORES;

    float* scr = nullptr;
    cudaGetSymbolAddress((void**)&scr, g_scratch);
    float* y1d    = scr + O_Y1D;
    float* y1T    = scr + O_Y1T;
    float* y2T    = scr + O_Y2T;
    float* p3max  = scr + O_P3MAX;
    float* p3min  = scr + O_P3MIN;
    float* margin = scr + O_MARGIN;
    float* newxyz = scr + O_NEWXYZ;
    float* wpad   = scr + O_WPAD;
    float* featT  = scr + O_FEATT;
    int* fgmask   = (int*)(scr + O_FGMASK);
    int* idxInt   = (int*)(scr + O_INDICES);
    int* ballIdx  = (int*)(scr + O_BALL);
    int* fpsPid   = (int*)(scr + O_FPSPID);

    gemm_fused<4><<<dim3(NCOLS1D / 128, 1), 256>>>(fw1, features, y1d, 128, NCOLS1D, 0);
    maskhead_kernel<<<NCOLS1D / 256, 256>>>(y1d, fg1, fb1, fw2, fbias2, outScores, margin);
    select_kernel<<<4, 1024>>>(margin, fgmask);

    cudaFuncSetAttribute(fps_kernel, cudaFuncAttributeMaxDynamicSharedMemorySize, 14336 * 12);
    fps_kernel<<<8, 1024, 14336 * 12>>>(xyz, fgmask, fpsPid, idxInt, outIdx);

    setup_kernel<<<80 + 8192, dim3(32, 8)>>>(w1, wpad, features, featT);
    ballq_kernel<<<NPOINT * BATCH / 8, 256>>>(xyz, idxInt, newxyz, outXyz, ballIdx);

    // conv1: NT=128, B gathered on the fly; K permuted [feat|xyz|pad]
    {
        auto k = conv_mma<KX1, 128, -1, 1, 0, 1>;
        size_t sm = (size_t)(128 + 128) * (KX1 + 4) * 4;
        cudaFuncSetAttribute(k, cudaFuncAttributeMaxDynamicSharedMemorySize, (int)sm);
        k<<<dim3(NCOLS2D / 128, 1), 256, sm>>>(wpad, featT, y1T, nullptr, nullptr,
                                               nullptr, nullptr, ballIdx, xyz, newxyz);
    }
    // conv2: NT=64 (occ 2), BN1+relu on B-load
    {
        auto k = conv_mma<128, 64, 1, 2, 0, 0>;
        size_t sm = (size_t)(128 + 64) * 132 * 4;
        cudaFuncSetAttribute(k, cudaFuncAttributeMaxDynamicSharedMemorySize, (int)sm);
        k<<<dim3(NCOLS2D / 64, 1), 256, sm>>>(w2, y1T, y2T, nullptr, nullptr, g1, b1,
                                              nullptr, nullptr, nullptr);
    }
    // conv3: NT=64 (occ 2), M=256 via grid.y=2, BN2+relu on B-load, pool fused
    {
        auto k = conv_mma<128, 64, 2, 3, 1, 0>;
        size_t sm = (size_t)(128 + 64) * 132 * 4;
        cudaFuncSetAttribute(k, cudaFuncAttributeMaxDynamicSharedMemorySize, (int)sm);
        k<<<dim3(NCOLS2D / 64, 2), 256, sm>>>(w3, y2T, nullptr, p3max, p3min, g2, b2,
                                              nullptr, nullptr, nullptr);
    }
    maxpool_final<<<(256 * 4096) / 256, 256>>>(p3max, p3min, g3, b3, outFeat);
}